// round 2
// baseline (speedup 1.0000x reference)
#include <cuda_runtime.h>
#include <math.h>

#define NN      50000
#define IN_DIM  128
#define OUT_DIM 32
#define HEADS   8
#define FF      256          // OUT_DIM * HEADS
#define EE      800000
#define SEM_HID 128

// ---------------- scratch (static device globals; no allocation) -------------
__device__ float g_feat[2][NN * FF];     // W-projected features per metapath
__device__ float g_out[2][NN * FF];      // aggregation accumulator, then z
__device__ float g_el[2][NN * HEADS];
__device__ float g_er[2][NN * HEADS];
__device__ float g_m[2][NN * HEADS];     // per-dst per-head running max
__device__ float g_denom[2][NN * HEADS];
__device__ float g_qsum[2];

// ---------------- helpers ----------------------------------------------------
__device__ __forceinline__ void atomicMaxFloat(float* addr, float v) {
    // sign-split trick: correct total order on float bit patterns
    if (v >= 0.0f) atomicMax((int*)addr, __float_as_int(v));
    else           atomicMin((unsigned int*)addr, __float_as_uint(v));
}

// ---------------- K0: init ---------------------------------------------------
__global__ void init_kernel() {
    const float NEG_INF = -__int_as_float(0x7f800000);
    for (int i = blockIdx.x * blockDim.x + threadIdx.x; i < NN * FF;
         i += gridDim.x * blockDim.x) {
        g_out[0][i] = 0.0f;
        g_out[1][i] = 0.0f;
        if (i < NN * HEADS) {
            g_denom[0][i] = 0.0f;
            g_denom[1][i] = 0.0f;
            g_m[0][i] = NEG_INF;
            g_m[1][i] = NEG_INF;
        }
        if (i < 2) g_qsum[i] = 0.0f;
    }
}

// ---------------- K1: fused GEMM  feat = h @ [W_a | W_b] ---------------------
// C is [NN x 512]; cols 0..255 -> g_feat[0], 256..511 -> g_feat[1]
#define BM 64
#define BN 64
#define BK 16
#define TM 4
#define TN 4
__global__ __launch_bounds__(256) void gemm_kernel(
    const float* __restrict__ h,
    const float* __restrict__ Wa,
    const float* __restrict__ Wb) {
    __shared__ float As[BK][BM];
    __shared__ float Bs[BK][BN];
    const int tid = threadIdx.x;
    const int tr = tid / 16, tc = tid % 16;
    const int rowBase = blockIdx.y * BM;
    const int colBase = blockIdx.x * BN;

    float acc[TM][TN];
#pragma unroll
    for (int i = 0; i < TM; i++)
#pragma unroll
        for (int j = 0; j < TN; j++) acc[i][j] = 0.0f;

    for (int k0 = 0; k0 < IN_DIM; k0 += BK) {
        // load A tile (BM x BK)
#pragma unroll
        for (int i = tid; i < BM * BK; i += 256) {
            int r = i / BK, c = i % BK;
            int gr = rowBase + r;
            As[c][r] = (gr < NN) ? h[gr * IN_DIM + k0 + c] : 0.0f;
        }
        // load B tile (BK x BN)
#pragma unroll
        for (int i = tid; i < BK * BN; i += 256) {
            int r = i / BN, c = i % BN;
            int gc = colBase + c;
            int gk = k0 + r;
            Bs[r][c] = (gc < FF) ? Wa[gk * FF + gc] : Wb[gk * FF + (gc - FF)];
        }
        __syncthreads();
#pragma unroll
        for (int k = 0; k < BK; k++) {
            float a[TM], b[TN];
#pragma unroll
            for (int i = 0; i < TM; i++) a[i] = As[k][tr * TM + i];
#pragma unroll
            for (int j = 0; j < TN; j++) b[j] = Bs[k][tc * TN + j];
#pragma unroll
            for (int i = 0; i < TM; i++)
#pragma unroll
                for (int j = 0; j < TN; j++) acc[i][j] += a[i] * b[j];
        }
        __syncthreads();
    }
#pragma unroll
    for (int i = 0; i < TM; i++) {
        int gr = rowBase + tr * TM + i;
        if (gr >= NN) continue;
#pragma unroll
        for (int j = 0; j < TN; j++) {
            int gc = colBase + tc * TN + j;
            if (gc < FF) g_feat[0][gr * FF + gc] = acc[i][j];
            else         g_feat[1][gr * FF + gc - FF] = acc[i][j];
        }
    }
}

// ---------------- K2: per-(node, head) attention logits el/er ----------------
__global__ void elr_kernel(const float* __restrict__ al_a,
                           const float* __restrict__ ar_a,
                           const float* __restrict__ al_b,
                           const float* __restrict__ ar_b) {
    int i = blockIdx.x * blockDim.x + threadIdx.x;
    if (i >= 2 * NN * HEADS) return;
    int p  = i / (NN * HEADS);
    int r  = i - p * (NN * HEADS);
    int n  = r / HEADS;
    int hd = r - n * HEADS;
    const float* al = p ? al_b : al_a;
    const float* ar = p ? ar_b : ar_a;
    const float* f  = &g_feat[p][n * FF + hd * OUT_DIM];
    float el = 0.0f, er = 0.0f;
#pragma unroll
    for (int j = 0; j < OUT_DIM; j++) {
        float v = f[j];
        el += v * al[hd * OUT_DIM + j];
        er += v * ar[hd * OUT_DIM + j];
    }
    g_el[p][r] = el;
    g_er[p][r] = er;
}

// ---------------- K3: edge max pass ------------------------------------------
__global__ void edge_max_kernel(const int* __restrict__ src_a,
                                const int* __restrict__ dst_a,
                                const int* __restrict__ src_b,
                                const int* __restrict__ dst_b) {
    int i = blockIdx.x * blockDim.x + threadIdx.x;
    if (i >= 2 * EE) return;
    int p = (i >= EE) ? 1 : 0;
    int e = i - p * EE;
    int s = p ? src_b[e] : src_a[e];
    int d = p ? dst_b[e] : dst_a[e];
    const float4* elp = (const float4*)&g_el[p][s * HEADS];
    const float4* erp = (const float4*)&g_er[p][d * HEADS];
    float4 el0 = elp[0], el1 = elp[1];
    float4 er0 = erp[0], er1 = erp[1];
    float ev[HEADS] = {el0.x + er0.x, el0.y + er0.y, el0.z + er0.z, el0.w + er0.w,
                       el1.x + er1.x, el1.y + er1.y, el1.z + er1.z, el1.w + er1.w};
#pragma unroll
    for (int hd = 0; hd < HEADS; hd++) {
        float x = ev[hd];
        x = (x > 0.0f) ? x : 0.2f * x;   // leaky_relu 0.2
        atomicMaxFloat(&g_m[p][d * HEADS + hd], x);
    }
}

// ---------------- K4: edge aggregate pass (warp per edge) --------------------
__global__ void edge_agg_kernel(const int* __restrict__ src_a,
                                const int* __restrict__ dst_a,
                                const int* __restrict__ src_b,
                                const int* __restrict__ dst_b) {
    int gw   = (blockIdx.x * blockDim.x + threadIdx.x) >> 5;   // global warp id
    int lane = threadIdx.x & 31;
    if (gw >= 2 * EE) return;
    int p = (gw >= EE) ? 1 : 0;
    int e = gw - p * EE;
    int s = p ? src_b[e] : src_a[e];
    int d = p ? dst_b[e] : dst_a[e];

    int hd = lane >> 2;   // 4 lanes per head, 8 consecutive cols each
    float x = g_el[p][s * HEADS + hd] + g_er[p][d * HEADS + hd];
    x = (x > 0.0f) ? x : 0.2f * x;
    float ex = __expf(x - g_m[p][d * HEADS + hd]);

    if ((lane & 3) == 0) atomicAdd(&g_denom[p][d * HEADS + hd], ex);

    const float4* fp = (const float4*)&g_feat[p][s * FF + lane * 8];
    float4 f0 = fp[0], f1 = fp[1];
    float* op = &g_out[p][d * FF + lane * 8];
    atomicAdd(op + 0, f0.x * ex);
    atomicAdd(op + 1, f0.y * ex);
    atomicAdd(op + 2, f0.z * ex);
    atomicAdd(op + 3, f0.w * ex);
    atomicAdd(op + 4, f1.x * ex);
    atomicAdd(op + 5, f1.y * ex);
    atomicAdd(op + 6, f1.z * ex);
    atomicAdd(op + 7, f1.w * ex);
}

// ---------------- K5: finalize (normalize + ELU -> z, semantic q) ------------
__global__ __launch_bounds__(SEM_HID) void finalize_kernel(
    const float* __restrict__ bias_a,
    const float* __restrict__ bias_b,
    const float* __restrict__ Wsem,
    const float* __restrict__ bsem,
    const float* __restrict__ wsem) {
    int n = blockIdx.x;
    int p = blockIdx.y;
    int t = threadIdx.x;                 // 128 threads
    __shared__ float zs[FF];
    __shared__ float red[SEM_HID];
    const float* bias = p ? bias_b : bias_a;

#pragma unroll
    for (int j = t; j < FF; j += SEM_HID) {
        int hd = j >> 5;
        float den = g_denom[p][n * HEADS + hd];
        den = (den > 0.0f) ? den : 1.0f;
        float v = g_out[p][n * FF + j] / den + bias[j];
        v = (v > 0.0f) ? v : (expf(v) - 1.0f);   // ELU
        zs[j] = v;
        g_out[p][n * FF + j] = v;                // store z in place
    }
    __syncthreads();

    float acc = bsem[t];
    for (int f = 0; f < FF; f++) acc += zs[f] * Wsem[f * SEM_HID + t];
    red[t] = tanhf(acc) * wsem[t];
    __syncthreads();
#pragma unroll
    for (int st = SEM_HID / 2; st > 0; st >>= 1) {
        if (t < st) red[t] += red[t + st];
        __syncthreads();
    }
    if (t == 0) atomicAdd(&g_qsum[p], red[0]);
}

// ---------------- K6: combine with semantic softmax --------------------------
__global__ void combine_kernel(float* __restrict__ out) {
    int i = blockIdx.x * blockDim.x + threadIdx.x;
    if (i >= NN * FF) return;
    float q0 = g_qsum[0] * (1.0f / NN);
    float q1 = g_qsum[1] * (1.0f / NN);
    float mx = fmaxf(q0, q1);
    float b0 = __expf(q0 - mx);
    float b1 = __expf(q1 - mx);
    float inv = 1.0f / (b0 + b1);
    out[i] = (g_out[0][i] * b0 + g_out[1][i] * b1) * inv;
}

// ---------------- launch -----------------------------------------------------
extern "C" void kernel_launch(void* const* d_in, const int* in_sizes, int n_in,
                              void* d_out, int out_size) {
    const float* h      = (const float*)d_in[0];
    const int*   src_a  = (const int*)  d_in[1];
    const int*   dst_a  = (const int*)  d_in[2];
    const int*   src_b  = (const int*)  d_in[3];
    const int*   dst_b  = (const int*)  d_in[4];
    const float* W_a    = (const float*)d_in[5];
    const float* al_a   = (const float*)d_in[6];
    const float* ar_a   = (const float*)d_in[7];
    const float* bias_a = (const float*)d_in[8];
    const float* W_b    = (const float*)d_in[9];
    const float* al_b   = (const float*)d_in[10];
    const float* ar_b   = (const float*)d_in[11];
    const float* bias_b = (const float*)d_in[12];
    const float* Wsem   = (const float*)d_in[13];
    const float* bsem   = (const float*)d_in[14];
    const float* wsem   = (const float*)d_in[15];
    float* out = (float*)d_out;

    (void)in_sizes; (void)n_in; (void)out_size;

    // K0: init
    init_kernel<<<4096, 256>>>();

    // K1: fused GEMM (cols: 512 = 2 metapaths x 256)
    {
        dim3 grid((2 * FF) / BN, (NN + BM - 1) / BM);
        gemm_kernel<<<grid, 256>>>(h, W_a, W_b);
    }

    // K2: el/er
    {
        int tot = 2 * NN * HEADS;
        elr_kernel<<<(tot + 255) / 256, 256>>>(al_a, ar_a, al_b, ar_b);
    }

    // K3: edge max
    {
        int tot = 2 * EE;
        edge_max_kernel<<<(tot + 255) / 256, 256>>>(src_a, dst_a, src_b, dst_b);
    }

    // K4: edge aggregate (one warp per edge)
    {
        long long tot = 2LL * EE * 32;
        edge_agg_kernel<<<(int)((tot + 255) / 256), 256>>>(src_a, dst_a, src_b, dst_b);
    }

    // K5: finalize + semantic q
    {
        dim3 grid(NN, 2);
        finalize_kernel<<<grid, SEM_HID>>>(bias_a, bias_b, Wsem, bsem, wsem);
    }

    // K6: combine
    combine_kernel<<<(NN * FF + 255) / 256, 256>>>(out);
}

// round 3
// speedup vs baseline: 2.3784x; 2.3784x over previous
#include <cuda_runtime.h>
#include <math.h>

#define NN      50000
#define IN_DIM  128
#define OUT_DIM 32
#define HEADS   8
#define FF      256          // OUT_DIM * HEADS
#define EE      800000
#define SEM_HID 128

// ---------------- scratch (static device globals; no allocation) -------------
__device__ float g_feat[2][NN * FF];       // W-projected features per metapath
__device__ float g_out[2][NN * FF];        // normalized aggregation -> z
__device__ float g_el[2][NN * HEADS];
__device__ float g_er[2][NN * HEADS];
__device__ float g_exs[2][EE * HEADS];     // exp(lrelu(e)) per edge per head (CSR order)
__device__ int   g_csrc[2][EE];            // CSR src node per slot
__device__ int   g_rowptr[2][NN + 1];
__device__ int   g_cnt[2][NN];
__device__ int   g_cursor[2][NN];
__device__ float g_qsum[2];

// ---------------- K0: init (counts + qsum only) ------------------------------
__global__ void init_kernel() {
    int i = blockIdx.x * blockDim.x + threadIdx.x;
    if (i < NN) {
        g_cnt[0][i] = 0;
        g_cnt[1][i] = 0;
    }
    if (i < 2) g_qsum[i] = 0.0f;
}

// ---------------- K1: fused GEMM  feat = h @ [W_a | W_b] ---------------------
#define BM 64
#define BN 64
#define BK 16
#define TM 4
#define TN 4
__global__ __launch_bounds__(256) void gemm_kernel(
    const float* __restrict__ h,
    const float* __restrict__ Wa,
    const float* __restrict__ Wb) {
    __shared__ float As[BK][BM];
    __shared__ float Bs[BK][BN];
    const int tid = threadIdx.x;
    const int tr = tid / 16, tc = tid % 16;
    const int rowBase = blockIdx.y * BM;
    const int colBase = blockIdx.x * BN;

    float acc[TM][TN];
#pragma unroll
    for (int i = 0; i < TM; i++)
#pragma unroll
        for (int j = 0; j < TN; j++) acc[i][j] = 0.0f;

    for (int k0 = 0; k0 < IN_DIM; k0 += BK) {
#pragma unroll
        for (int i = tid; i < BM * BK; i += 256) {
            int r = i / BK, c = i % BK;
            int gr = rowBase + r;
            As[c][r] = (gr < NN) ? h[gr * IN_DIM + k0 + c] : 0.0f;
        }
#pragma unroll
        for (int i = tid; i < BK * BN; i += 256) {
            int r = i / BN, c = i % BN;
            int gc = colBase + c;
            int gk = k0 + r;
            Bs[r][c] = (gc < FF) ? Wa[gk * FF + gc] : Wb[gk * FF + (gc - FF)];
        }
        __syncthreads();
#pragma unroll
        for (int k = 0; k < BK; k++) {
            float a[TM], b[TN];
#pragma unroll
            for (int i = 0; i < TM; i++) a[i] = As[k][tr * TM + i];
#pragma unroll
            for (int j = 0; j < TN; j++) b[j] = Bs[k][tc * TN + j];
#pragma unroll
            for (int i = 0; i < TM; i++)
#pragma unroll
                for (int j = 0; j < TN; j++) acc[i][j] += a[i] * b[j];
        }
        __syncthreads();
    }
#pragma unroll
    for (int i = 0; i < TM; i++) {
        int gr = rowBase + tr * TM + i;
        if (gr >= NN) continue;
#pragma unroll
        for (int j = 0; j < TN; j++) {
            int gc = colBase + tc * TN + j;
            if (gc < FF) g_feat[0][gr * FF + gc] = acc[i][j];
            else         g_feat[1][gr * FF + gc - FF] = acc[i][j];
        }
    }
}

// ---------------- K2: per-(node, head) attention logits el/er ----------------
__global__ void elr_kernel(const float* __restrict__ al_a,
                           const float* __restrict__ ar_a,
                           const float* __restrict__ al_b,
                           const float* __restrict__ ar_b) {
    int i = blockIdx.x * blockDim.x + threadIdx.x;
    if (i >= 2 * NN * HEADS) return;
    int p  = i / (NN * HEADS);
    int r  = i - p * (NN * HEADS);
    int n  = r / HEADS;
    int hd = r - n * HEADS;
    const float* al = p ? al_b : al_a;
    const float* ar = p ? ar_b : ar_a;
    const float* f  = &g_feat[p][n * FF + hd * OUT_DIM];
    float el = 0.0f, er = 0.0f;
#pragma unroll
    for (int j = 0; j < OUT_DIM; j++) {
        float v = f[j];
        el += v * al[hd * OUT_DIM + j];
        er += v * ar[hd * OUT_DIM + j];
    }
    g_el[p][r] = el;
    g_er[p][r] = er;
}

// ---------------- K3: degree histogram ---------------------------------------
__global__ void count_kernel(const int* __restrict__ dst_a,
                             const int* __restrict__ dst_b) {
    int i = blockIdx.x * blockDim.x + threadIdx.x;
    if (i >= 2 * EE) return;
    int p = (i >= EE) ? 1 : 0;
    int e = i - p * EE;
    int d = p ? dst_b[e] : dst_a[e];
    atomicAdd(&g_cnt[p][d], 1);
}

// ---------------- K4: exclusive scan -> rowptr + cursor (1 block / metapath) -
__global__ __launch_bounds__(1024) void scan_kernel() {
    int p = blockIdx.x;
    int t = threadIdx.x;
    __shared__ int sh[1024];
    __shared__ int offset;
    if (t == 0) { offset = 0; g_rowptr[p][0] = 0; }
    __syncthreads();
    for (int base = 0; base < NN; base += 1024) {
        int i = base + t;
        int v = (i < NN) ? g_cnt[p][i] : 0;
        sh[t] = v;
        __syncthreads();
#pragma unroll
        for (int st = 1; st < 1024; st <<= 1) {
            int x = 0;
            if (t >= st) x = sh[t - st];
            __syncthreads();
            if (t >= st) sh[t] += x;
            __syncthreads();
        }
        int incl = sh[t] + offset;
        if (i < NN) {
            g_rowptr[p][i + 1] = incl;
            g_cursor[p][i]     = incl - v;
        }
        int chunk_total = sh[1023];
        __syncthreads();
        if (t == 0) offset += chunk_total;
        __syncthreads();
    }
}

// ---------------- K5: scatter edges into CSR ---------------------------------
__global__ void scatter_kernel(const int* __restrict__ src_a,
                               const int* __restrict__ dst_a,
                               const int* __restrict__ src_b,
                               const int* __restrict__ dst_b) {
    int i = blockIdx.x * blockDim.x + threadIdx.x;
    if (i >= 2 * EE) return;
    int p = (i >= EE) ? 1 : 0;
    int e = i - p * EE;
    int s = p ? src_b[e] : src_a[e];
    int d = p ? dst_b[e] : dst_a[e];
    int pos = atomicAdd(&g_cursor[p][d], 1);
    g_csrc[p][pos] = s;
}

// ---------------- K6: per-dst aggregation (gather, no atomics) ---------------
// 64 threads per (dst, metapath); thread owns 4 contiguous columns.
__global__ __launch_bounds__(64) void agg_kernel() {
    const int d = blockIdx.x;
    const int p = blockIdx.y;
    const int t = threadIdx.x;               // 0..63
    const int start = g_rowptr[p][d];
    const int end   = g_rowptr[p][d + 1];

    __shared__ float er_sh[HEADS];
    __shared__ float den_sh[HEADS];
    if (t < HEADS) {
        er_sh[t]  = g_er[p][d * HEADS + t];
        den_sh[t] = 0.0f;
    }
    __syncthreads();

    // phase A: ex = exp(lrelu(el[s]+er[d])), local denom
    float den[HEADS];
#pragma unroll
    for (int k = 0; k < HEADS; k++) den[k] = 0.0f;
    for (int j = start + t; j < end; j += 64) {
        int s = g_csrc[p][j];
        const float4* elp = (const float4*)&g_el[p][s * HEADS];
        float4 a = elp[0], b = elp[1];
        float e[HEADS] = {a.x + er_sh[0], a.y + er_sh[1], a.z + er_sh[2], a.w + er_sh[3],
                          b.x + er_sh[4], b.y + er_sh[5], b.z + er_sh[6], b.w + er_sh[7]};
        float4 x0, x1;
        float ex[HEADS];
#pragma unroll
        for (int k = 0; k < HEADS; k++) {
            float xx = e[k];
            xx = (xx > 0.0f) ? xx : 0.2f * xx;     // leaky_relu(0.2)
            ex[k] = __expf(xx);
            den[k] += ex[k];
        }
        x0 = make_float4(ex[0], ex[1], ex[2], ex[3]);
        x1 = make_float4(ex[4], ex[5], ex[6], ex[7]);
        float4* xo = (float4*)&g_exs[p][j * HEADS];
        xo[0] = x0;
        xo[1] = x1;
    }
    // reduce denom across 64 threads
    const int lane = t & 31;
#pragma unroll
    for (int k = 0; k < HEADS; k++) {
        float v = den[k];
#pragma unroll
        for (int o = 16; o > 0; o >>= 1) v += __shfl_down_sync(0xffffffffu, v, o);
        if (lane == 0) atomicAdd(&den_sh[k], v);
    }
    __syncthreads();

    const int hd = t >> 3;                   // head for cols [t*4, t*4+4)
    float dv = den_sh[hd];
    float invd = (dv > 0.0f) ? 1.0f / dv : 1.0f;

    // phase B: gather-accumulate features (float4 per thread)
    float4 acc = make_float4(0.f, 0.f, 0.f, 0.f);
    int j = start;
    int s_cur = (j < end) ? g_csrc[p][j] : 0;
    for (; j < end; j++) {
        int s_next = (j + 1 < end) ? g_csrc[p][j + 1] : 0;
        float ex = g_exs[p][j * HEADS + hd];
        float4 f = *(const float4*)&g_feat[p][s_cur * FF + t * 4];
        acc.x += f.x * ex;
        acc.y += f.y * ex;
        acc.z += f.z * ex;
        acc.w += f.w * ex;
        s_cur = s_next;
    }
    acc.x *= invd; acc.y *= invd; acc.z *= invd; acc.w *= invd;
    *(float4*)&g_out[p][d * FF + t * 4] = acc;
}

// ---------------- K7: finalize (bias + ELU -> z, semantic q) -----------------
__global__ __launch_bounds__(SEM_HID) void finalize_kernel(
    const float* __restrict__ bias_a,
    const float* __restrict__ bias_b,
    const float* __restrict__ Wsem,
    const float* __restrict__ bsem,
    const float* __restrict__ wsem) {
    int n = blockIdx.x;
    int p = blockIdx.y;
    int t = threadIdx.x;                 // 128 threads
    __shared__ float zs[FF];
    __shared__ float red[SEM_HID];
    const float* bias = p ? bias_b : bias_a;

#pragma unroll
    for (int j = t; j < FF; j += SEM_HID) {
        float v = g_out[p][n * FF + j] + bias[j];
        v = (v > 0.0f) ? v : (expf(v) - 1.0f);   // ELU
        zs[j] = v;
        g_out[p][n * FF + j] = v;                // store z in place
    }
    __syncthreads();

    float acc = bsem[t];
    for (int f = 0; f < FF; f++) acc += zs[f] * Wsem[f * SEM_HID + t];
    red[t] = tanhf(acc) * wsem[t];
    __syncthreads();
#pragma unroll
    for (int st = SEM_HID / 2; st > 0; st >>= 1) {
        if (t < st) red[t] += red[t + st];
        __syncthreads();
    }
    if (t == 0) atomicAdd(&g_qsum[p], red[0]);
}

// ---------------- K8: combine with semantic softmax --------------------------
__global__ void combine_kernel(float* __restrict__ out) {
    int i = blockIdx.x * blockDim.x + threadIdx.x;
    if (i >= NN * FF) return;
    float q0 = g_qsum[0] * (1.0f / NN);
    float q1 = g_qsum[1] * (1.0f / NN);
    float mx = fmaxf(q0, q1);
    float b0 = __expf(q0 - mx);
    float b1 = __expf(q1 - mx);
    float inv = 1.0f / (b0 + b1);
    out[i] = (g_out[0][i] * b0 + g_out[1][i] * b1) * inv;
}

// ---------------- launch -----------------------------------------------------
extern "C" void kernel_launch(void* const* d_in, const int* in_sizes, int n_in,
                              void* d_out, int out_size) {
    const float* h      = (const float*)d_in[0];
    const int*   src_a  = (const int*)  d_in[1];
    const int*   dst_a  = (const int*)  d_in[2];
    const int*   src_b  = (const int*)  d_in[3];
    const int*   dst_b  = (const int*)  d_in[4];
    const float* al_a   = (const float*)d_in[6];
    const float* ar_a   = (const float*)d_in[7];
    const float* bias_a = (const float*)d_in[8];
    const float* W_a    = (const float*)d_in[5];
    const float* W_b    = (const float*)d_in[9];
    const float* al_b   = (const float*)d_in[10];
    const float* ar_b   = (const float*)d_in[11];
    const float* bias_b = (const float*)d_in[12];
    const float* Wsem   = (const float*)d_in[13];
    const float* bsem   = (const float*)d_in[14];
    const float* wsem   = (const float*)d_in[15];
    float* out = (float*)d_out;

    (void)in_sizes; (void)n_in; (void)out_size;

    // K0: init counts
    init_kernel<<<(NN + 255) / 256, 256>>>();

    // K1: fused GEMM
    {
        dim3 grid((2 * FF) / BN, (NN + BM - 1) / BM);
        gemm_kernel<<<grid, 256>>>(h, W_a, W_b);
    }

    // K2: el/er
    {
        int tot = 2 * NN * HEADS;
        elr_kernel<<<(tot + 255) / 256, 256>>>(al_a, ar_a, al_b, ar_b);
    }

    // K3: degree histogram
    count_kernel<<<(2 * EE + 255) / 256, 256>>>(dst_a, dst_b);

    // K4: scan -> rowptr + cursor
    scan_kernel<<<2, 1024>>>();

    // K5: scatter into CSR
    scatter_kernel<<<(2 * EE + 255) / 256, 256>>>(src_a, dst_a, src_b, dst_b);

    // K6: per-dst gather aggregation
    {
        dim3 grid(NN, 2);
        agg_kernel<<<grid, 64>>>();
    }

    // K7: finalize + semantic q
    {
        dim3 grid(NN, 2);
        finalize_kernel<<<grid, SEM_HID>>>(bias_a, bias_b, Wsem, bsem, wsem);
    }

    // K8: combine
    combine_kernel<<<(NN * FF + 255) / 256, 256>>>(out);
}

// round 4
// speedup vs baseline: 4.6606x; 1.9596x over previous
#include <cuda_runtime.h>
#include <math.h>

#define NN      50000
#define IN_DIM  128
#define OUT_DIM 32
#define HEADS   8
#define FF      256          // OUT_DIM * HEADS
#define EE      800000
#define SEM_HID 128
#define NCHUNK  49           // ceil(NN / 1024)

// ---------------- scratch (static device globals; no allocation) -------------
__device__ float g_feat[2][NN * FF];       // W-projected features per metapath
__device__ float g_out[2][NN * FF];        // z (bias+ELU applied in agg epilogue)
__device__ float g_el[2][NN * HEADS];
__device__ float g_er[2][NN * HEADS];
__device__ float g_exs[2][EE * HEADS];     // exp(lrelu(e)) per edge per head (CSR order)
__device__ int   g_csrc[2][EE];            // CSR src node per slot
__device__ int   g_rowptr[2][NN + 1];
__device__ int   g_cnt[2][NN];
__device__ int   g_cursor[2][NN];
__device__ int   g_bsum[2][NCHUNK];
__device__ float g_q[2 * NN * SEM_HID];    // semantic pre-activation
__device__ float g_qsum[2];

// ---------------- K0: init ---------------------------------------------------
__global__ void init_kernel() {
    int i = blockIdx.x * blockDim.x + threadIdx.x;
    if (i < NN) {
        g_cnt[0][i] = 0;
        g_cnt[1][i] = 0;
    }
    if (i < 2) g_qsum[i] = 0.0f;
}

// ---------------- K1: fused GEMM  feat = h @ [W_a | W_b] ---------------------
// 128x64 tile, TM=8 x TN=4, 256 threads, float4 global loads.
#define BM 128
#define BN 64
#define BK 16
#define TM 8
#define TN 4
__global__ __launch_bounds__(256) void gemm_kernel(
    const float* __restrict__ h,
    const float* __restrict__ Wa,
    const float* __restrict__ Wb) {
    __shared__ float As[BK][BM];
    __shared__ float Bs[BK][BN];
    const int tid = threadIdx.x;
    const int tr = tid / 16, tc = tid % 16;
    const int rowBase = blockIdx.y * BM;
    const int colBase = blockIdx.x * BN;

    float acc[TM][TN];
#pragma unroll
    for (int i = 0; i < TM; i++)
#pragma unroll
        for (int j = 0; j < TN; j++) acc[i][j] = 0.0f;

    for (int k0 = 0; k0 < IN_DIM; k0 += BK) {
        // A tile: 128 rows x 16 cols = 512 float4
#pragma unroll
        for (int it = 0; it < 2; it++) {
            int idx = tid + it * 256;          // 0..511
            int r = idx >> 2, c4 = idx & 3;
            int gr = rowBase + r;
            float4 v = make_float4(0.f, 0.f, 0.f, 0.f);
            if (gr < NN) v = *(const float4*)&h[gr * IN_DIM + k0 + c4 * 4];
            As[c4 * 4 + 0][r] = v.x;
            As[c4 * 4 + 1][r] = v.y;
            As[c4 * 4 + 2][r] = v.z;
            As[c4 * 4 + 3][r] = v.w;
        }
        // B tile: 16 rows x 64 cols = 256 float4
        {
            int idx = tid;
            int r = idx >> 4, c4 = idx & 15;
            int gc = colBase + c4 * 4;
            int gk = k0 + r;
            float4 v;
            if (gc < FF) v = *(const float4*)&Wa[gk * FF + gc];
            else         v = *(const float4*)&Wb[gk * FF + (gc - FF)];
            *(float4*)&Bs[r][c4 * 4] = v;
        }
        __syncthreads();
#pragma unroll
        for (int k = 0; k < BK; k++) {
            float a[TM], b[TN];
#pragma unroll
            for (int i = 0; i < TM; i++) a[i] = As[k][tr * TM + i];
#pragma unroll
            for (int j = 0; j < TN; j++) b[j] = Bs[k][tc * TN + j];
#pragma unroll
            for (int i = 0; i < TM; i++)
#pragma unroll
                for (int j = 0; j < TN; j++) acc[i][j] += a[i] * b[j];
        }
        __syncthreads();
    }
    const int gc0 = colBase + tc * TN;
    const int p = (gc0 >= FF) ? 1 : 0;
    const int cc = p ? gc0 - FF : gc0;
#pragma unroll
    for (int i = 0; i < TM; i++) {
        int gr = rowBase + tr * TM + i;
        if (gr >= NN) continue;
        float4 v = make_float4(acc[i][0], acc[i][1], acc[i][2], acc[i][3]);
        *(float4*)&g_feat[p][gr * FF + cc] = v;
    }
}

// ---------------- K2: per-(node, head) attention logits el/er ----------------
__global__ void elr_kernel(const float* __restrict__ al_a,
                           const float* __restrict__ ar_a,
                           const float* __restrict__ al_b,
                           const float* __restrict__ ar_b) {
    int i = blockIdx.x * blockDim.x + threadIdx.x;
    if (i >= 2 * NN * HEADS) return;
    int p  = i / (NN * HEADS);
    int r  = i - p * (NN * HEADS);
    int n  = r / HEADS;
    int hd = r - n * HEADS;
    const float* al = p ? al_b : al_a;
    const float* ar = p ? ar_b : ar_a;
    const float4* f4  = (const float4*)&g_feat[p][n * FF + hd * OUT_DIM];
    const float4* al4 = (const float4*)&al[hd * OUT_DIM];
    const float4* ar4 = (const float4*)&ar[hd * OUT_DIM];
    float el = 0.0f, er = 0.0f;
#pragma unroll
    for (int j = 0; j < OUT_DIM / 4; j++) {
        float4 fv = f4[j], av = al4[j], rv = ar4[j];
        el += fv.x * av.x + fv.y * av.y + fv.z * av.z + fv.w * av.w;
        er += fv.x * rv.x + fv.y * rv.y + fv.z * rv.z + fv.w * rv.w;
    }
    g_el[p][r] = el;
    g_er[p][r] = er;
}

// ---------------- K3: degree histogram ---------------------------------------
__global__ void count_kernel(const int* __restrict__ dst_a,
                             const int* __restrict__ dst_b) {
    int i = blockIdx.x * blockDim.x + threadIdx.x;
    if (i >= 2 * EE) return;
    int p = (i >= EE) ? 1 : 0;
    int e = i - p * EE;
    int d = p ? dst_b[e] : dst_a[e];
    atomicAdd(&g_cnt[p][d], 1);
}

// ---------------- K4a: per-chunk reduce --------------------------------------
__global__ __launch_bounds__(256) void reduce_kernel() {
    int p = blockIdx.y, c = blockIdx.x, t = threadIdx.x;
    int base = c * 1024;
    int v = 0;
#pragma unroll
    for (int k = 0; k < 4; k++) {
        int i = base + t + k * 256;
        if (i < NN) v += g_cnt[p][i];
    }
    __shared__ int sh[256];
    sh[t] = v;
    __syncthreads();
#pragma unroll
    for (int st = 128; st > 0; st >>= 1) {
        if (t < st) sh[t] += sh[t + st];
        __syncthreads();
    }
    if (t == 0) g_bsum[p][c] = sh[0];
}

// ---------------- K4b: tiny serial scan of chunk sums ------------------------
__global__ void bscan_kernel() {
    int p = blockIdx.x;
    if (threadIdx.x != 0) return;
    int run = 0;
    for (int c = 0; c < NCHUNK; c++) {
        int tmp = g_bsum[p][c];
        g_bsum[p][c] = run;
        run += tmp;
    }
}

// ---------------- K4c: per-chunk scan apply -> rowptr + cursor ---------------
__global__ __launch_bounds__(1024) void scanapply_kernel() {
    int p = blockIdx.y, c = blockIdx.x, t = threadIdx.x;
    int i = c * 1024 + t;
    int v = (i < NN) ? g_cnt[p][i] : 0;
    int lane = t & 31, w = t >> 5;
    int x = v;
#pragma unroll
    for (int o = 1; o < 32; o <<= 1) {
        int y = __shfl_up_sync(0xffffffffu, x, o);
        if (lane >= o) x += y;
    }
    __shared__ int ws[32];
    if (lane == 31) ws[w] = x;
    __syncthreads();
    if (w == 0) {
        int y = ws[lane];
#pragma unroll
        for (int o = 1; o < 32; o <<= 1) {
            int z = __shfl_up_sync(0xffffffffu, y, o);
            if (lane >= o) y += z;
        }
        ws[lane] = y;
    }
    __syncthreads();
    int incl = x + ((w > 0) ? ws[w - 1] : 0) + g_bsum[p][c];
    if (i < NN) {
        g_rowptr[p][i + 1] = incl;
        g_cursor[p][i]     = incl - v;
    }
    if (i == 0) g_rowptr[p][0] = 0;
}

// ---------------- K5: scatter into CSR + compute edge exp --------------------
__global__ void scatter_kernel(const int* __restrict__ src_a,
                               const int* __restrict__ dst_a,
                               const int* __restrict__ src_b,
                               const int* __restrict__ dst_b) {
    int i = blockIdx.x * blockDim.x + threadIdx.x;
    if (i >= 2 * EE) return;
    int p = (i >= EE) ? 1 : 0;
    int e = i - p * EE;
    int s = p ? src_b[e] : src_a[e];
    int d = p ? dst_b[e] : dst_a[e];
    int pos = atomicAdd(&g_cursor[p][d], 1);
    g_csrc[p][pos] = s;

    const float4* elp = (const float4*)&g_el[p][s * HEADS];
    const float4* erp = (const float4*)&g_er[p][d * HEADS];
    float4 a = elp[0], b = elp[1];
    float4 c = erp[0], dd = erp[1];
    float ev[HEADS] = {a.x + c.x, a.y + c.y, a.z + c.z, a.w + c.w,
                       b.x + dd.x, b.y + dd.y, b.z + dd.z, b.w + dd.w};
    float ex[HEADS];
#pragma unroll
    for (int k = 0; k < HEADS; k++) {
        float xx = ev[k];
        xx = (xx > 0.0f) ? xx : 0.2f * xx;     // leaky_relu(0.2)
        ex[k] = __expf(xx);
    }
    float4* xo = (float4*)&g_exs[p][pos * HEADS];
    xo[0] = make_float4(ex[0], ex[1], ex[2], ex[3]);
    xo[1] = make_float4(ex[4], ex[5], ex[6], ex[7]);
}

// ---------------- K6: per-dst aggregation + bias + ELU (no atomics) ----------
// 64 threads per (dst, metapath); thread owns 4 contiguous columns.
__global__ __launch_bounds__(64) void agg_kernel(const float* __restrict__ bias_a,
                                                 const float* __restrict__ bias_b) {
    const int d = blockIdx.x;
    const int p = blockIdx.y;
    const int t = threadIdx.x;               // 0..63
    const int start = g_rowptr[p][d];
    const int end   = g_rowptr[p][d + 1];
    const int hd = t >> 3;                   // head for cols [t*4, t*4+4)

    float4 acc = make_float4(0.f, 0.f, 0.f, 0.f);
    float den = 0.0f;
    int j = start;
    int s = (j < end) ? g_csrc[p][j] : 0;
    for (; j < end; j++) {
        int s_nx = (j + 1 < end) ? g_csrc[p][j + 1] : 0;
        float ex = g_exs[p][j * HEADS + hd];
        float4 f = *(const float4*)&g_feat[p][s * FF + t * 4];
        acc.x += f.x * ex;
        acc.y += f.y * ex;
        acc.z += f.z * ex;
        acc.w += f.w * ex;
        den += ex;
        s = s_nx;
    }
    float invd = (den > 0.0f) ? 1.0f / den : 1.0f;
    const float* bias = p ? bias_b : bias_a;
    float4 bv = *(const float4*)&bias[t * 4];
    float4 z;
    z.x = acc.x * invd + bv.x;
    z.y = acc.y * invd + bv.y;
    z.z = acc.z * invd + bv.z;
    z.w = acc.w * invd + bv.w;
    z.x = (z.x > 0.0f) ? z.x : (expf(z.x) - 1.0f);
    z.y = (z.y > 0.0f) ? z.y : (expf(z.y) - 1.0f);
    z.z = (z.z > 0.0f) ? z.z : (expf(z.z) - 1.0f);
    z.w = (z.w > 0.0f) ? z.w : (expf(z.w) - 1.0f);
    *(float4*)&g_out[p][d * FF + t * 4] = z;
}

// ---------------- K7: semantic GEMM  Q = Z @ Wsem ----------------------------
// M = 2*NN rows (Z = g_out flattened), K = 256, N = 128.
__global__ __launch_bounds__(256) void gemm2_kernel(const float* __restrict__ Wsem) {
    __shared__ float As[BK][BM];
    __shared__ float Bs[BK][BN];
    const float* Z = (const float*)g_out;
    const int M = 2 * NN;
    const int tid = threadIdx.x;
    const int tr = tid / 16, tc = tid % 16;
    const int rowBase = blockIdx.y * BM;
    const int colBase = blockIdx.x * BN;

    float acc[TM][TN];
#pragma unroll
    for (int i = 0; i < TM; i++)
#pragma unroll
        for (int j = 0; j < TN; j++) acc[i][j] = 0.0f;

    for (int k0 = 0; k0 < FF; k0 += BK) {
#pragma unroll
        for (int it = 0; it < 2; it++) {
            int idx = tid + it * 256;
            int r = idx >> 2, c4 = idx & 3;
            int gr = rowBase + r;
            float4 v = make_float4(0.f, 0.f, 0.f, 0.f);
            if (gr < M) v = *(const float4*)&Z[gr * FF + k0 + c4 * 4];
            As[c4 * 4 + 0][r] = v.x;
            As[c4 * 4 + 1][r] = v.y;
            As[c4 * 4 + 2][r] = v.z;
            As[c4 * 4 + 3][r] = v.w;
        }
        {
            int idx = tid;
            int r = idx >> 4, c4 = idx & 15;
            float4 v = *(const float4*)&Wsem[(k0 + r) * SEM_HID + colBase + c4 * 4];
            *(float4*)&Bs[r][c4 * 4] = v;
        }
        __syncthreads();
#pragma unroll
        for (int k = 0; k < BK; k++) {
            float a[TM], b[TN];
#pragma unroll
            for (int i = 0; i < TM; i++) a[i] = As[k][tr * TM + i];
#pragma unroll
            for (int j = 0; j < TN; j++) b[j] = Bs[k][tc * TN + j];
#pragma unroll
            for (int i = 0; i < TM; i++)
#pragma unroll
                for (int j = 0; j < TN; j++) acc[i][j] += a[i] * b[j];
        }
        __syncthreads();
    }
    const int gc0 = colBase + tc * TN;
#pragma unroll
    for (int i = 0; i < TM; i++) {
        int gr = rowBase + tr * TM + i;
        if (gr >= M) continue;
        *(float4*)&g_q[gr * SEM_HID + gc0] =
            make_float4(acc[i][0], acc[i][1], acc[i][2], acc[i][3]);
    }
}

// ---------------- K8: q reduce (tanh . wsem, sum over nodes) -----------------
__global__ __launch_bounds__(256) void qreduce_kernel(const float* __restrict__ bsem,
                                                      const float* __restrict__ wsem) {
    int w = threadIdx.x >> 5, lane = threadIdx.x & 31;
    int row = blockIdx.x * 8 + w;            // < 2*NN (blocks aligned to metapath)
    float4 v  = *(const float4*)&g_q[row * SEM_HID + lane * 4];
    float4 bs = *(const float4*)&bsem[lane * 4];
    float4 ws = *(const float4*)&wsem[lane * 4];
    float acc = tanhf(v.x + bs.x) * ws.x + tanhf(v.y + bs.y) * ws.y +
                tanhf(v.z + bs.z) * ws.z + tanhf(v.w + bs.w) * ws.w;
#pragma unroll
    for (int o = 16; o > 0; o >>= 1) acc += __shfl_down_sync(0xffffffffu, acc, o);
    __shared__ float sh[8];
    if (lane == 0) sh[w] = acc;
    __syncthreads();
    if (threadIdx.x == 0) {
        float s = 0.f;
#pragma unroll
        for (int k = 0; k < 8; k++) s += sh[k];
        int p = (row >= NN) ? 1 : 0;         // all 8 rows in a block share p
        atomicAdd(&g_qsum[p], s);
    }
}

// ---------------- K9: combine with semantic softmax --------------------------
__global__ void combine_kernel(float* __restrict__ out) {
    int i = blockIdx.x * blockDim.x + threadIdx.x;
    if (i >= NN * FF) return;
    float q0 = g_qsum[0] * (1.0f / NN);
    float q1 = g_qsum[1] * (1.0f / NN);
    float mx = fmaxf(q0, q1);
    float b0 = __expf(q0 - mx);
    float b1 = __expf(q1 - mx);
    float inv = 1.0f / (b0 + b1);
    out[i] = (g_out[0][i] * b0 + g_out[1][i] * b1) * inv;
}

// ---------------- launch -----------------------------------------------------
extern "C" void kernel_launch(void* const* d_in, const int* in_sizes, int n_in,
                              void* d_out, int out_size) {
    const float* h      = (const float*)d_in[0];
    const int*   src_a  = (const int*)  d_in[1];
    const int*   dst_a  = (const int*)  d_in[2];
    const int*   src_b  = (const int*)  d_in[3];
    const int*   dst_b  = (const int*)  d_in[4];
    const float* W_a    = (const float*)d_in[5];
    const float* al_a   = (const float*)d_in[6];
    const float* ar_a   = (const float*)d_in[7];
    const float* bias_a = (const float*)d_in[8];
    const float* W_b    = (const float*)d_in[9];
    const float* al_b   = (const float*)d_in[10];
    const float* ar_b   = (const float*)d_in[11];
    const float* bias_b = (const float*)d_in[12];
    const float* Wsem   = (const float*)d_in[13];
    const float* bsem   = (const float*)d_in[14];
    const float* wsem   = (const float*)d_in[15];
    float* out = (float*)d_out;

    (void)in_sizes; (void)n_in; (void)out_size;

    init_kernel<<<(NN + 255) / 256, 256>>>();

    {   // K1: projection GEMM
        dim3 grid((2 * FF) / BN, (NN + BM - 1) / BM);
        gemm_kernel<<<grid, 256>>>(h, W_a, W_b);
    }

    {   // K2: el/er
        int tot = 2 * NN * HEADS;
        elr_kernel<<<(tot + 255) / 256, 256>>>(al_a, ar_a, al_b, ar_b);
    }

    count_kernel<<<(2 * EE + 255) / 256, 256>>>(dst_a, dst_b);

    {   // K4: 3-phase scan
        dim3 grid(NCHUNK, 2);
        reduce_kernel<<<grid, 256>>>();
        bscan_kernel<<<2, 32>>>();
        scanapply_kernel<<<grid, 1024>>>();
    }

    scatter_kernel<<<(2 * EE + 255) / 256, 256>>>(src_a, dst_a, src_b, dst_b);

    {   // K6: gather aggregation + bias + ELU
        dim3 grid(NN, 2);
        agg_kernel<<<grid, 64>>>(bias_a, bias_b);
    }

    {   // K7: semantic GEMM
        dim3 grid(SEM_HID / BN, (2 * NN + BM - 1) / BM);
        gemm2_kernel<<<grid, 256>>>(Wsem);
    }

    // K8: q reduce (2*NN / 8 rows per block; 100000/8 = 12500)
    qreduce_kernel<<<(2 * NN) / 8, 256>>>(bsem, wsem);

    // K9: combine
    combine_kernel<<<(NN * FF + 255) / 256, 256>>>(out);
}

// round 6
// speedup vs baseline: 7.5021x; 1.6097x over previous
#include <cuda_runtime.h>
#include <math.h>
#include <stdint.h>

#define NN      50000
#define IN_DIM  128
#define OUT_DIM 32
#define HEADS   8
#define FF      256          // OUT_DIM * HEADS
#define EE      800000
#define SEM_HID 128
#define NCHUNK  49           // ceil(NN / 1024)

// ---------------- scratch (static device globals; no allocation) -------------
__device__ float g_feat[2][NN * FF];       // W-projected features per metapath
__device__ float g_out[2][NN * FF];        // z (bias+ELU applied in agg epilogue)
__device__ float g_el[2][NN * HEADS];
__device__ float g_er[2][NN * HEADS];
__device__ float g_exs[2][EE * HEADS];     // exp(lrelu(e)) per edge per head
__device__ int   g_csrc[2][EE];            // CSR src node per slot
__device__ int   g_rowptr[2][NN + 1];
__device__ int   g_cnt[2][NN];
__device__ int   g_cursor[2][NN];
__device__ int   g_bsum[2][NCHUNK];
__device__ float g_qsum[2];

// ---------------- tf32 helpers -----------------------------------------------
__device__ __forceinline__ uint32_t f2tf32(float x) {
    uint32_t r;
    asm("cvt.rna.tf32.f32 %0, %1;" : "=r"(r) : "f"(x));
    return r;
}
__device__ __forceinline__ void mma_tf32(float c[4],
                                         uint32_t a0, uint32_t a1, uint32_t a2, uint32_t a3,
                                         uint32_t b0, uint32_t b1) {
    asm volatile(
        "mma.sync.aligned.m16n8k8.row.col.f32.tf32.tf32.f32 "
        "{%0,%1,%2,%3}, {%4,%5,%6,%7}, {%8,%9}, {%0,%1,%2,%3};\n"
        : "+f"(c[0]), "+f"(c[1]), "+f"(c[2]), "+f"(c[3])
        : "r"(a0), "r"(a1), "r"(a2), "r"(a3), "r"(b0), "r"(b1));
}
__device__ __forceinline__ float tanh_fast(float x) {
    float r;
    asm("tanh.approx.f32 %0, %1;" : "=f"(r) : "f"(x));
    return r;
}

// ---------------- K0: init ---------------------------------------------------
__global__ void init_kernel() {
    int i = blockIdx.x * blockDim.x + threadIdx.x;
    if (i < NN) {
        g_cnt[0][i] = 0;
        g_cnt[1][i] = 0;
    }
    if (i < 2) g_qsum[i] = 0.0f;
}

// ---------------- K1: tf32 GEMM  feat = h @ [W_a|W_b]  + fused el/er ---------
#define GBM 128
#define GBN 64
#define GBK 16
#define APAD 8
#define BPAD 8
__global__ __launch_bounds__(256) void gemm1_kernel(
    const float* __restrict__ h,
    const float* __restrict__ Wa,
    const float* __restrict__ Wb,
    const float* __restrict__ al_a,
    const float* __restrict__ ar_a,
    const float* __restrict__ al_b,
    const float* __restrict__ ar_b) {
    __shared__ uint32_t As[GBK][GBM + APAD];
    __shared__ uint32_t Bs[GBK][GBN + BPAD];
    const int tid = threadIdx.x;
    const int lane = tid & 31;
    const int wid = tid >> 5;
    const int mBase = (wid >> 1) * 32;
    const int nBase = (wid & 1) * 32;
    const int rowBase = blockIdx.y * GBM;
    const int colBase = blockIdx.x * GBN;

    float acc[2][4][4];
#pragma unroll
    for (int mf = 0; mf < 2; mf++)
#pragma unroll
        for (int nf = 0; nf < 4; nf++)
#pragma unroll
            for (int c = 0; c < 4; c++) acc[mf][nf][c] = 0.0f;

    for (int k0 = 0; k0 < IN_DIM; k0 += GBK) {
#pragma unroll
        for (int it = 0; it < 2; it++) {
            int idx = tid + it * 256;
            int r = idx >> 2, c4 = idx & 3;
            int gr = rowBase + r;
            float4 v = make_float4(0.f, 0.f, 0.f, 0.f);
            if (gr < NN) v = *(const float4*)&h[gr * IN_DIM + k0 + c4 * 4];
            As[c4 * 4 + 0][r] = f2tf32(v.x);
            As[c4 * 4 + 1][r] = f2tf32(v.y);
            As[c4 * 4 + 2][r] = f2tf32(v.z);
            As[c4 * 4 + 3][r] = f2tf32(v.w);
        }
        {
            int r = tid >> 4, c4 = tid & 15;
            int gc = colBase + c4 * 4;
            const float* W = (gc >= FF) ? Wb : Wa;
            int cc = gc & (FF - 1);
            float4 v = *(const float4*)&W[(k0 + r) * FF + cc];
            Bs[r][c4 * 4 + 0] = f2tf32(v.x);
            Bs[r][c4 * 4 + 1] = f2tf32(v.y);
            Bs[r][c4 * 4 + 2] = f2tf32(v.z);
            Bs[r][c4 * 4 + 3] = f2tf32(v.w);
        }
        __syncthreads();
#pragma unroll
        for (int ks = 0; ks < GBK; ks += 8) {
            uint32_t a[2][4], b[4][2];
#pragma unroll
            for (int mf = 0; mf < 2; mf++) {
                int row = mBase + mf * 16 + (lane >> 2);
                a[mf][0] = As[ks + (lane & 3)][row];
                a[mf][1] = As[ks + (lane & 3)][row + 8];
                a[mf][2] = As[ks + 4 + (lane & 3)][row];
                a[mf][3] = As[ks + 4 + (lane & 3)][row + 8];
            }
#pragma unroll
            for (int nf = 0; nf < 4; nf++) {
                int col = nBase + nf * 8 + (lane >> 2);
                b[nf][0] = Bs[ks + (lane & 3)][col];
                b[nf][1] = Bs[ks + 4 + (lane & 3)][col];
            }
#pragma unroll
            for (int mf = 0; mf < 2; mf++)
#pragma unroll
                for (int nf = 0; nf < 4; nf++)
                    mma_tf32(acc[mf][nf], a[mf][0], a[mf][1], a[mf][2], a[mf][3],
                             b[nf][0], b[nf][1]);
        }
        __syncthreads();
    }

    // ---- epilogue: write feat + fused el/er (warp N-span == one head) ----
    const int gc0 = colBase + nBase;          // 32-aligned
    const int hg = gc0 >> 5;                  // global head 0..15
    const int p = hg >> 3;
    const int hd = hg & 7;
    const float* al = p ? al_b : al_a;
    const float* ar = p ? ar_b : ar_a;
    float alv[8], arv[8];
#pragma unroll
    for (int nf = 0; nf < 4; nf++) {
        int c = nf * 8 + 2 * (lane & 3);
        alv[nf * 2 + 0] = al[hd * OUT_DIM + c];
        alv[nf * 2 + 1] = al[hd * OUT_DIM + c + 1];
        arv[nf * 2 + 0] = ar[hd * OUT_DIM + c];
        arv[nf * 2 + 1] = ar[hd * OUT_DIM + c + 1];
    }
    const int ccBase = gc0 & 255;
#pragma unroll
    for (int mf = 0; mf < 2; mf++) {
#pragma unroll
        for (int half = 0; half < 2; half++) {
            int gr = rowBase + mBase + mf * 16 + half * 8 + (lane >> 2);
            float el = 0.0f, er = 0.0f;
            if (gr < NN) {
#pragma unroll
                for (int nf = 0; nf < 4; nf++) {
                    float v0 = acc[mf][nf][half * 2 + 0];
                    float v1 = acc[mf][nf][half * 2 + 1];
                    int cc = ccBase + nf * 8 + 2 * (lane & 3);
                    *(float2*)&g_feat[p][gr * FF + cc] = make_float2(v0, v1);
                    el += v0 * alv[nf * 2] + v1 * alv[nf * 2 + 1];
                    er += v0 * arv[nf * 2] + v1 * arv[nf * 2 + 1];
                }
            }
            el += __shfl_xor_sync(0xffffffffu, el, 1);
            el += __shfl_xor_sync(0xffffffffu, el, 2);
            er += __shfl_xor_sync(0xffffffffu, er, 1);
            er += __shfl_xor_sync(0xffffffffu, er, 2);
            if ((lane & 3) == 0 && gr < NN) {
                g_el[p][gr * HEADS + hd] = el;
                g_er[p][gr * HEADS + hd] = er;
            }
        }
    }
}

// ---------------- K3: degree histogram ---------------------------------------
__global__ void count_kernel(const int* __restrict__ dst_a,
                             const int* __restrict__ dst_b) {
    int i = blockIdx.x * blockDim.x + threadIdx.x;
    if (i >= 2 * EE) return;
    int p = (i >= EE) ? 1 : 0;
    int e = i - p * EE;
    int d = p ? dst_b[e] : dst_a[e];
    atomicAdd(&g_cnt[p][d], 1);
}

// ---------------- K4a: per-chunk reduce --------------------------------------
__global__ __launch_bounds__(256) void reduce_kernel() {
    int p = blockIdx.y, c = blockIdx.x, t = threadIdx.x;
    int base = c * 1024;
    int v = 0;
#pragma unroll
    for (int k = 0; k < 4; k++) {
        int i = base + t + k * 256;
        if (i < NN) v += g_cnt[p][i];
    }
    __shared__ int sh[256];
    sh[t] = v;
    __syncthreads();
#pragma unroll
    for (int st = 128; st > 0; st >>= 1) {
        if (t < st) sh[t] += sh[t + st];
        __syncthreads();
    }
    if (t == 0) g_bsum[p][c] = sh[0];
}

// ---------------- K4b: tiny serial scan of chunk sums ------------------------
__global__ void bscan_kernel() {
    int p = blockIdx.x;
    if (threadIdx.x != 0) return;
    int run = 0;
    for (int c = 0; c < NCHUNK; c++) {
        int tmp = g_bsum[p][c];
        g_bsum[p][c] = run;
        run += tmp;
    }
}

// ---------------- K4c: per-chunk scan apply -> rowptr + cursor ---------------
__global__ __launch_bounds__(1024) void scanapply_kernel() {
    int p = blockIdx.y, c = blockIdx.x, t = threadIdx.x;
    int i = c * 1024 + t;
    int v = (i < NN) ? g_cnt[p][i] : 0;
    int lane = t & 31, w = t >> 5;
    int x = v;
#pragma unroll
    for (int o = 1; o < 32; o <<= 1) {
        int y = __shfl_up_sync(0xffffffffu, x, o);
        if (lane >= o) x += y;
    }
    __shared__ int ws[32];
    if (lane == 31) ws[w] = x;
    __syncthreads();
    if (w == 0) {
        int y = ws[lane];
#pragma unroll
        for (int o = 1; o < 32; o <<= 1) {
            int z = __shfl_up_sync(0xffffffffu, y, o);
            if (lane >= o) y += z;
        }
        ws[lane] = y;
    }
    __syncthreads();
    int incl = x + ((w > 0) ? ws[w - 1] : 0) + g_bsum[p][c];
    if (i < NN) {
        g_rowptr[p][i + 1] = incl;
        g_cursor[p][i]     = incl - v;
    }
    if (i == 0) g_rowptr[p][0] = 0;
}

// ---------------- K5: scatter into CSR + compute edge exp --------------------
__global__ void scatter_kernel(const int* __restrict__ src_a,
                               const int* __restrict__ dst_a,
                               const int* __restrict__ src_b,
                               const int* __restrict__ dst_b) {
    int i = blockIdx.x * blockDim.x + threadIdx.x;
    if (i >= 2 * EE) return;
    int p = (i >= EE) ? 1 : 0;
    int e = i - p * EE;
    int s = p ? src_b[e] : src_a[e];
    int d = p ? dst_b[e] : dst_a[e];
    int pos = atomicAdd(&g_cursor[p][d], 1);
    g_csrc[p][pos] = s;

    const float4* elp = (const float4*)&g_el[p][s * HEADS];
    const float4* erp = (const float4*)&g_er[p][d * HEADS];
    float4 a = elp[0], b = elp[1];
    float4 c = erp[0], dd = erp[1];
    float ev[HEADS] = {a.x + c.x, a.y + c.y, a.z + c.z, a.w + c.w,
                       b.x + dd.x, b.y + dd.y, b.z + dd.z, b.w + dd.w};
    float ex[HEADS];
#pragma unroll
    for (int k = 0; k < HEADS; k++) {
        float xx = ev[k];
        xx = (xx > 0.0f) ? xx : 0.2f * xx;     // leaky_relu(0.2)
        ex[k] = __expf(xx);
    }
    float4* xo = (float4*)&g_exs[p][pos * HEADS];
    xo[0] = make_float4(ex[0], ex[1], ex[2], ex[3]);
    xo[1] = make_float4(ex[4], ex[5], ex[6], ex[7]);
}

// ---------------- K6: per-dst aggregation + bias + ELU (no atomics) ----------
__global__ __launch_bounds__(64) void agg_kernel(const float* __restrict__ bias_a,
                                                 const float* __restrict__ bias_b) {
    const int d = blockIdx.x;
    const int p = blockIdx.y;
    const int t = threadIdx.x;               // 0..63
    const int start = g_rowptr[p][d];
    const int end   = g_rowptr[p][d + 1];
    const int hd = t >> 3;                   // head for cols [t*4, t*4+4)

    float4 acc = make_float4(0.f, 0.f, 0.f, 0.f);
    float den = 0.0f;
    int j = start;
    int s = (j < end) ? g_csrc[p][j] : 0;
    for (; j < end; j++) {
        int s_nx = (j + 1 < end) ? g_csrc[p][j + 1] : 0;
        float ex = g_exs[p][j * HEADS + hd];
        float4 f = *(const float4*)&g_feat[p][s * FF + t * 4];
        acc.x += f.x * ex;
        acc.y += f.y * ex;
        acc.z += f.z * ex;
        acc.w += f.w * ex;
        den += ex;
        s = s_nx;
    }
    float invd = (den > 0.0f) ? 1.0f / den : 1.0f;
    const float* bias = p ? bias_b : bias_a;
    float4 bv = *(const float4*)&bias[t * 4];
    float4 z;
    z.x = acc.x * invd + bv.x;
    z.y = acc.y * invd + bv.y;
    z.z = acc.z * invd + bv.z;
    z.w = acc.w * invd + bv.w;
    z.x = (z.x > 0.0f) ? z.x : (expf(z.x) - 1.0f);
    z.y = (z.y > 0.0f) ? z.y : (expf(z.y) - 1.0f);
    z.z = (z.z > 0.0f) ? z.z : (expf(z.z) - 1.0f);
    z.w = (z.w > 0.0f) ? z.w : (expf(z.w) - 1.0f);
    *(float4*)&g_out[p][d * FF + t * 4] = z;
}

// ---------------- K7: tf32 GEMM  q = Z @ Wsem  + fused tanh.wsem reduce ------
__global__ __launch_bounds__(256) void gemm2_kernel(
    const float* __restrict__ Wsem,
    const float* __restrict__ bsem,
    const float* __restrict__ wsem) {
    __shared__ uint32_t As[GBK][GBM + APAD];
    __shared__ uint32_t Bs[GBK][GBN + BPAD];
    const float* Z = (const float*)g_out;
    const int M = 2 * NN;
    const int tid = threadIdx.x;
    const int lane = tid & 31;
    const int wid = tid >> 5;
    const int mBase = (wid >> 1) * 32;
    const int nBase = (wid & 1) * 32;
    const int rowBase = blockIdx.y * GBM;
    const int colBase = blockIdx.x * GBN;

    float acc[2][4][4];
#pragma unroll
    for (int mf = 0; mf < 2; mf++)
#pragma unroll
        for (int nf = 0; nf < 4; nf++)
#pragma unroll
            for (int c = 0; c < 4; c++) acc[mf][nf][c] = 0.0f;

    for (int k0 = 0; k0 < FF; k0 += GBK) {
#pragma unroll
        for (int it = 0; it < 2; it++) {
            int idx = tid + it * 256;
            int r = idx >> 2, c4 = idx & 3;
            int gr = rowBase + r;
            float4 v = make_float4(0.f, 0.f, 0.f, 0.f);
            if (gr < M) v = *(const float4*)&Z[gr * FF + k0 + c4 * 4];
            As[c4 * 4 + 0][r] = f2tf32(v.x);
            As[c4 * 4 + 1][r] = f2tf32(v.y);
            As[c4 * 4 + 2][r] = f2tf32(v.z);
            As[c4 * 4 + 3][r] = f2tf32(v.w);
        }
        {
            int r = tid >> 4, c4 = tid & 15;
            float4 v = *(const float4*)&Wsem[(k0 + r) * SEM_HID + colBase + c4 * 4];
            Bs[r][c4 * 4 + 0] = f2tf32(v.x);
            Bs[r][c4 * 4 + 1] = f2tf32(v.y);
            Bs[r][c4 * 4 + 2] = f2tf32(v.z);
            Bs[r][c4 * 4 + 3] = f2tf32(v.w);
        }
        __syncthreads();
#pragma unroll
        for (int ks = 0; ks < GBK; ks += 8) {
            uint32_t a[2][4], b[4][2];
#pragma unroll
            for (int mf = 0; mf < 2; mf++) {
                int row = mBase + mf * 16 + (lane >> 2);
                a[mf][0] = As[ks + (lane & 3)][row];
                a[mf][1] = As[ks + (lane & 3)][row + 8];
                a[mf][2] = As[ks + 4 + (lane & 3)][row];
                a[mf][3] = As[ks + 4 + (lane & 3)][row + 8];
            }
#pragma unroll
            for (int nf = 0; nf < 4; nf++) {
                int col = nBase + nf * 8 + (lane >> 2);
                b[nf][0] = Bs[ks + (lane & 3)][col];
                b[nf][1] = Bs[ks + 4 + (lane & 3)][col];
            }
#pragma unroll
            for (int mf = 0; mf < 2; mf++)
#pragma unroll
                for (int nf = 0; nf < 4; nf++)
                    mma_tf32(acc[mf][nf], a[mf][0], a[mf][1], a[mf][2], a[mf][3],
                             b[nf][0], b[nf][1]);
        }
        __syncthreads();
    }

    // ---- epilogue: tanh(q + bsem) . wsem, reduce, atomic into g_qsum --------
    float bsv[8], wsv[8];
#pragma unroll
    for (int nf = 0; nf < 4; nf++) {
        int gc = colBase + nBase + nf * 8 + 2 * (lane & 3);
        bsv[nf * 2 + 0] = bsem[gc];
        bsv[nf * 2 + 1] = bsem[gc + 1];
        wsv[nf * 2 + 0] = wsem[gc];
        wsv[nf * 2 + 1] = wsem[gc + 1];
    }
    float sp0 = 0.0f, sp1 = 0.0f;
#pragma unroll
    for (int mf = 0; mf < 2; mf++) {
#pragma unroll
        for (int half = 0; half < 2; half++) {
            int gr = rowBase + mBase + mf * 16 + half * 8 + (lane >> 2);
            if (gr < M) {
                float rs = 0.0f;
#pragma unroll
                for (int nf = 0; nf < 4; nf++) {
                    rs += tanh_fast(acc[mf][nf][half * 2 + 0] + bsv[nf * 2 + 0]) * wsv[nf * 2 + 0];
                    rs += tanh_fast(acc[mf][nf][half * 2 + 1] + bsv[nf * 2 + 1]) * wsv[nf * 2 + 1];
                }
                if (gr < NN) sp0 += rs; else sp1 += rs;
            }
        }
    }
#pragma unroll
    for (int o = 16; o > 0; o >>= 1) {
        sp0 += __shfl_down_sync(0xffffffffu, sp0, o);
        sp1 += __shfl_down_sync(0xffffffffu, sp1, o);
    }
    __shared__ float sh[8][2];
    if (lane == 0) { sh[wid][0] = sp0; sh[wid][1] = sp1; }
    __syncthreads();
    if (tid == 0) {
        float s0 = 0.f, s1 = 0.f;
#pragma unroll
        for (int k = 0; k < 8; k++) { s0 += sh[k][0]; s1 += sh[k][1]; }
        if (s0 != 0.0f) atomicAdd(&g_qsum[0], s0);
        if (s1 != 0.0f) atomicAdd(&g_qsum[1], s1);
    }
}

// ---------------- K9: combine with semantic softmax --------------------------
__global__ void combine_kernel(float* __restrict__ out) {
    int i = blockIdx.x * blockDim.x + threadIdx.x;
    if (i >= NN * FF) return;
    float q0 = g_qsum[0] * (1.0f / NN);
    float q1 = g_qsum[1] * (1.0f / NN);
    float mx = fmaxf(q0, q1);
    float b0 = __expf(q0 - mx);
    float b1 = __expf(q1 - mx);
    float inv = 1.0f / (b0 + b1);
    out[i] = (g_out[0][i] * b0 + g_out[1][i] * b1) * inv;
}

// ---------------- launch -----------------------------------------------------
extern "C" void kernel_launch(void* const* d_in, const int* in_sizes, int n_in,
                              void* d_out, int out_size) {
    const float* h      = (const float*)d_in[0];
    const int*   src_a  = (const int*)  d_in[1];
    const int*   dst_a  = (const int*)  d_in[2];
    const int*   src_b  = (const int*)  d_in[3];
    const int*   dst_b  = (const int*)  d_in[4];
    const float* W_a    = (const float*)d_in[5];
    const float* al_a   = (const float*)d_in[6];
    const float* ar_a   = (const float*)d_in[7];
    const float* bias_a = (const float*)d_in[8];
    const float* W_b    = (const float*)d_in[9];
    const float* al_b   = (const float*)d_in[10];
    const float* ar_b   = (const float*)d_in[11];
    const float* bias_b = (const float*)d_in[12];
    const float* Wsem   = (const float*)d_in[13];
    const float* bsem   = (const float*)d_in[14];
    const float* wsem   = (const float*)d_in[15];
    float* out = (float*)d_out;

    (void)in_sizes; (void)n_in; (void)out_size;

    init_kernel<<<(NN + 255) / 256, 256>>>();

    {   // K1: projection GEMM (tf32 TC) + fused el/er
        dim3 grid((2 * FF) / GBN, (NN + GBM - 1) / GBM);
        gemm1_kernel<<<grid, 256>>>(h, W_a, W_b, al_a, ar_a, al_b, ar_b);
    }

    count_kernel<<<(2 * EE + 255) / 256, 256>>>(dst_a, dst_b);

    {   // 3-phase scan
        dim3 grid(NCHUNK, 2);
        reduce_kernel<<<grid, 256>>>();
        bscan_kernel<<<2, 32>>>();
        scanapply_kernel<<<grid, 1024>>>();
    }

    scatter_kernel<<<(2 * EE + 255) / 256, 256>>>(src_a, dst_a, src_b, dst_b);

    {   // gather aggregation + bias + ELU
        dim3 grid(NN, 2);
        agg_kernel<<<grid, 64>>>(bias_a, bias_b);
    }

    {   // semantic GEMM (tf32 TC) + fused tanh.wsem reduction
        dim3 grid(SEM_HID / GBN, (2 * NN + GBM - 1) / GBM);
        gemm2_kernel<<<grid, 256>>>(Wsem, bsem, wsem);
    }

    combine_kernel<<<(NN * FF + 255) / 256, 256>>>(out);
}

// round 7
// speedup vs baseline: 7.6378x; 1.0181x over previous
#include <cuda_runtime.h>
#include <cuda_fp16.h>
#include <math.h>
#include <stdint.h>

#define NN      50000
#define IN_DIM  128
#define OUT_DIM 32
#define HEADS   8
#define FF      256          // OUT_DIM * HEADS
#define EE      800000
#define SEM_HID 128
#define NCHUNK  49           // ceil(NN / 1024)

// ---------------- scratch (static device globals; no allocation) -------------
__device__ __half g_feat16[2][NN * FF];    // W-projected features (fp16, agg-only)
__device__ float  g_out[2][NN * FF];       // z (bias+ELU applied in agg epilogue)
__device__ float  g_el[2][NN * HEADS];
__device__ float  g_er[2][NN * HEADS];
__device__ int    g_csrc[2][EE];           // CSR src node per slot
__device__ int    g_rowptr[2][NN + 1];
__device__ int    g_cnt[2][NN];
__device__ int    g_cursor[2][NN];
__device__ int    g_bsum[2][NCHUNK];
__device__ float  g_qsum[2];

// ---------------- tf32 helpers -----------------------------------------------
__device__ __forceinline__ uint32_t f2tf32(float x) {
    uint32_t r;
    asm("cvt.rna.tf32.f32 %0, %1;" : "=r"(r) : "f"(x));
    return r;
}
__device__ __forceinline__ void mma_tf32(float c[4],
                                         uint32_t a0, uint32_t a1, uint32_t a2, uint32_t a3,
                                         uint32_t b0, uint32_t b1) {
    asm volatile(
        "mma.sync.aligned.m16n8k8.row.col.f32.tf32.tf32.f32 "
        "{%0,%1,%2,%3}, {%4,%5,%6,%7}, {%8,%9}, {%0,%1,%2,%3};\n"
        : "+f"(c[0]), "+f"(c[1]), "+f"(c[2]), "+f"(c[3])
        : "r"(a0), "r"(a1), "r"(a2), "r"(a3), "r"(b0), "r"(b1));
}
__device__ __forceinline__ float tanh_fast(float x) {
    float r;
    asm("tanh.approx.f32 %0, %1;" : "=f"(r) : "f"(x));
    return r;
}

// ---------------- K0: init ---------------------------------------------------
__global__ void init_kernel() {
    int i = blockIdx.x * blockDim.x + threadIdx.x;
    if (i < NN) {
        g_cnt[0][i] = 0;
        g_cnt[1][i] = 0;
    }
    if (i < 2) g_qsum[i] = 0.0f;
}

// ---------------- K1: tf32 GEMM  feat = h @ [W_a|W_b]  + fused el/er ---------
#define GBM 128
#define GBN 64
#define GBK 16
#define APAD 8
#define BPAD 8
__global__ __launch_bounds__(256) void gemm1_kernel(
    const float* __restrict__ h,
    const float* __restrict__ Wa,
    const float* __restrict__ Wb,
    const float* __restrict__ al_a,
    const float* __restrict__ ar_a,
    const float* __restrict__ al_b,
    const float* __restrict__ ar_b) {
    __shared__ uint32_t As[GBK][GBM + APAD];
    __shared__ uint32_t Bs[GBK][GBN + BPAD];
    const int tid = threadIdx.x;
    const int lane = tid & 31;
    const int wid = tid >> 5;
    const int mBase = (wid >> 1) * 32;
    const int nBase = (wid & 1) * 32;
    const int rowBase = blockIdx.y * GBM;
    const int colBase = blockIdx.x * GBN;

    float acc[2][4][4];
#pragma unroll
    for (int mf = 0; mf < 2; mf++)
#pragma unroll
        for (int nf = 0; nf < 4; nf++)
#pragma unroll
            for (int c = 0; c < 4; c++) acc[mf][nf][c] = 0.0f;

    for (int k0 = 0; k0 < IN_DIM; k0 += GBK) {
#pragma unroll
        for (int it = 0; it < 2; it++) {
            int idx = tid + it * 256;
            int r = idx >> 2, c4 = idx & 3;
            int gr = rowBase + r;
            float4 v = make_float4(0.f, 0.f, 0.f, 0.f);
            if (gr < NN) v = *(const float4*)&h[gr * IN_DIM + k0 + c4 * 4];
            As[c4 * 4 + 0][r] = f2tf32(v.x);
            As[c4 * 4 + 1][r] = f2tf32(v.y);
            As[c4 * 4 + 2][r] = f2tf32(v.z);
            As[c4 * 4 + 3][r] = f2tf32(v.w);
        }
        {
            int r = tid >> 4, c4 = tid & 15;
            int gc = colBase + c4 * 4;
            const float* W = (gc >= FF) ? Wb : Wa;
            int cc = gc & (FF - 1);
            float4 v = *(const float4*)&W[(k0 + r) * FF + cc];
            Bs[r][c4 * 4 + 0] = f2tf32(v.x);
            Bs[r][c4 * 4 + 1] = f2tf32(v.y);
            Bs[r][c4 * 4 + 2] = f2tf32(v.z);
            Bs[r][c4 * 4 + 3] = f2tf32(v.w);
        }
        __syncthreads();
#pragma unroll
        for (int ks = 0; ks < GBK; ks += 8) {
            uint32_t a[2][4], b[4][2];
#pragma unroll
            for (int mf = 0; mf < 2; mf++) {
                int row = mBase + mf * 16 + (lane >> 2);
                a[mf][0] = As[ks + (lane & 3)][row];
                a[mf][1] = As[ks + (lane & 3)][row + 8];
                a[mf][2] = As[ks + 4 + (lane & 3)][row];
                a[mf][3] = As[ks + 4 + (lane & 3)][row + 8];
            }
#pragma unroll
            for (int nf = 0; nf < 4; nf++) {
                int col = nBase + nf * 8 + (lane >> 2);
                b[nf][0] = Bs[ks + (lane & 3)][col];
                b[nf][1] = Bs[ks + 4 + (lane & 3)][col];
            }
#pragma unroll
            for (int mf = 0; mf < 2; mf++)
#pragma unroll
                for (int nf = 0; nf < 4; nf++)
                    mma_tf32(acc[mf][nf], a[mf][0], a[mf][1], a[mf][2], a[mf][3],
                             b[nf][0], b[nf][1]);
        }
        __syncthreads();
    }

    // ---- epilogue: write feat (fp16) + fused el/er (warp N-span == one head)
    const int gc0 = colBase + nBase;          // 32-aligned
    const int hg = gc0 >> 5;                  // global head 0..15
    const int p = hg >> 3;
    const int hd = hg & 7;
    const float* al = p ? al_b : al_a;
    const float* ar = p ? ar_b : ar_a;
    float alv[8], arv[8];
#pragma unroll
    for (int nf = 0; nf < 4; nf++) {
        int c = nf * 8 + 2 * (lane & 3);
        alv[nf * 2 + 0] = al[hd * OUT_DIM + c];
        alv[nf * 2 + 1] = al[hd * OUT_DIM + c + 1];
        arv[nf * 2 + 0] = ar[hd * OUT_DIM + c];
        arv[nf * 2 + 1] = ar[hd * OUT_DIM + c + 1];
    }
    const int ccBase = gc0 & 255;
#pragma unroll
    for (int mf = 0; mf < 2; mf++) {
#pragma unroll
        for (int half = 0; half < 2; half++) {
            int gr = rowBase + mBase + mf * 16 + half * 8 + (lane >> 2);
            float el = 0.0f, er = 0.0f;
            if (gr < NN) {
#pragma unroll
                for (int nf = 0; nf < 4; nf++) {
                    float v0 = acc[mf][nf][half * 2 + 0];
                    float v1 = acc[mf][nf][half * 2 + 1];
                    int cc = ccBase + nf * 8 + 2 * (lane & 3);
                    *(__half2*)&g_feat16[p][gr * FF + cc] = __floats2half2_rn(v0, v1);
                    el += v0 * alv[nf * 2] + v1 * alv[nf * 2 + 1];
                    er += v0 * arv[nf * 2] + v1 * arv[nf * 2 + 1];
                }
            }
            el += __shfl_xor_sync(0xffffffffu, el, 1);
            el += __shfl_xor_sync(0xffffffffu, el, 2);
            er += __shfl_xor_sync(0xffffffffu, er, 1);
            er += __shfl_xor_sync(0xffffffffu, er, 2);
            if ((lane & 3) == 0 && gr < NN) {
                g_el[p][gr * HEADS + hd] = el;
                g_er[p][gr * HEADS + hd] = er;
            }
        }
    }
}

// ---------------- K3: degree histogram ---------------------------------------
__global__ void count_kernel(const int* __restrict__ dst_a,
                             const int* __restrict__ dst_b) {
    int i = blockIdx.x * blockDim.x + threadIdx.x;
    if (i >= 2 * EE) return;
    int p = (i >= EE) ? 1 : 0;
    int e = i - p * EE;
    int d = p ? dst_b[e] : dst_a[e];
    atomicAdd(&g_cnt[p][d], 1);
}

// ---------------- K4a: per-chunk reduce --------------------------------------
__global__ __launch_bounds__(256) void reduce_kernel() {
    int p = blockIdx.y, c = blockIdx.x, t = threadIdx.x;
    int base = c * 1024;
    int v = 0;
#pragma unroll
    for (int k = 0; k < 4; k++) {
        int i = base + t + k * 256;
        if (i < NN) v += g_cnt[p][i];
    }
    __shared__ int sh[256];
    sh[t] = v;
    __syncthreads();
#pragma unroll
    for (int st = 128; st > 0; st >>= 1) {
        if (t < st) sh[t] += sh[t + st];
        __syncthreads();
    }
    if (t == 0) g_bsum[p][c] = sh[0];
}

// ---------------- K4b: tiny serial scan of chunk sums ------------------------
__global__ void bscan_kernel() {
    int p = blockIdx.x;
    if (threadIdx.x != 0) return;
    int run = 0;
    for (int c = 0; c < NCHUNK; c++) {
        int tmp = g_bsum[p][c];
        g_bsum[p][c] = run;
        run += tmp;
    }
}

// ---------------- K4c: per-chunk scan apply -> rowptr + cursor ---------------
__global__ __launch_bounds__(1024) void scanapply_kernel() {
    int p = blockIdx.y, c = blockIdx.x, t = threadIdx.x;
    int i = c * 1024 + t;
    int v = (i < NN) ? g_cnt[p][i] : 0;
    int lane = t & 31, w = t >> 5;
    int x = v;
#pragma unroll
    for (int o = 1; o < 32; o <<= 1) {
        int y = __shfl_up_sync(0xffffffffu, x, o);
        if (lane >= o) x += y;
    }
    __shared__ int ws[32];
    if (lane == 31) ws[w] = x;
    __syncthreads();
    if (w == 0) {
        int y = ws[lane];
#pragma unroll
        for (int o = 1; o < 32; o <<= 1) {
            int z = __shfl_up_sync(0xffffffffu, y, o);
            if (lane >= o) y += z;
        }
        ws[lane] = y;
    }
    __syncthreads();
    int incl = x + ((w > 0) ? ws[w - 1] : 0) + g_bsum[p][c];
    if (i < NN) {
        g_rowptr[p][i + 1] = incl;
        g_cursor[p][i]     = incl - v;
    }
    if (i == 0) g_rowptr[p][0] = 0;
}

// ---------------- K5: scatter into CSR (slim: cursor + csrc only) ------------
__global__ void scatter_kernel(const int* __restrict__ src_a,
                               const int* __restrict__ dst_a,
                               const int* __restrict__ src_b,
                               const int* __restrict__ dst_b) {
    int i = blockIdx.x * blockDim.x + threadIdx.x;
    if (i >= 2 * EE) return;
    int p = (i >= EE) ? 1 : 0;
    int e = i - p * EE;
    int s = p ? src_b[e] : src_a[e];
    int d = p ? dst_b[e] : dst_a[e];
    int pos = atomicAdd(&g_cursor[p][d], 1);
    g_csrc[p][pos] = s;
}

// ---------------- K6: per-dst aggregation + softmax + bias + ELU -------------
// 64 threads per (dst, metapath); thread owns 4 contiguous columns (8 bytes fp16).
__global__ __launch_bounds__(64) void agg_kernel(const float* __restrict__ bias_a,
                                                 const float* __restrict__ bias_b) {
    const int d = blockIdx.x;
    const int p = blockIdx.y;
    const int t = threadIdx.x;               // 0..63
    const int start = g_rowptr[p][d];
    const int end   = g_rowptr[p][d + 1];
    const int hd = t >> 3;                   // head for cols [t*4, t*4+4)

    const float er = __ldg(&g_er[p][d * HEADS + hd]);
    const __half* fbase = &g_feat16[p][0];
    const float*  elbase = &g_el[p][0];
    const int*    csrc   = &g_csrc[p][0];

    float4 acc = make_float4(0.f, 0.f, 0.f, 0.f);
    float den = 0.0f;

    int j = start;
    for (; j + 1 < end; j += 2) {
        int s0 = csrc[j];
        int s1 = csrc[j + 1];
        float el0 = __ldg(&elbase[s0 * HEADS + hd]);
        float el1 = __ldg(&elbase[s1 * HEADS + hd]);
        uint2 r0 = *(const uint2*)&fbase[s0 * FF + t * 4];
        uint2 r1 = *(const uint2*)&fbase[s1 * FF + t * 4];
        float x0 = el0 + er; x0 = (x0 > 0.0f) ? x0 : 0.2f * x0;
        float x1 = el1 + er; x1 = (x1 > 0.0f) ? x1 : 0.2f * x1;
        float ex0 = __expf(x0);
        float ex1 = __expf(x1);
        den += ex0 + ex1;
        float2 a0 = __half22float2(*(const __half2*)&r0.x);
        float2 b0 = __half22float2(*(const __half2*)&r0.y);
        float2 a1 = __half22float2(*(const __half2*)&r1.x);
        float2 b1 = __half22float2(*(const __half2*)&r1.y);
        acc.x += a0.x * ex0 + a1.x * ex1;
        acc.y += a0.y * ex0 + a1.y * ex1;
        acc.z += b0.x * ex0 + b1.x * ex1;
        acc.w += b0.y * ex0 + b1.y * ex1;
    }
    if (j < end) {
        int s0 = csrc[j];
        float el0 = __ldg(&elbase[s0 * HEADS + hd]);
        uint2 r0 = *(const uint2*)&fbase[s0 * FF + t * 4];
        float x0 = el0 + er; x0 = (x0 > 0.0f) ? x0 : 0.2f * x0;
        float ex0 = __expf(x0);
        den += ex0;
        float2 a0 = __half22float2(*(const __half2*)&r0.x);
        float2 b0 = __half22float2(*(const __half2*)&r0.y);
        acc.x += a0.x * ex0;
        acc.y += a0.y * ex0;
        acc.z += b0.x * ex0;
        acc.w += b0.y * ex0;
    }

    float invd = (den > 0.0f) ? 1.0f / den : 1.0f;
    const float* bias = p ? bias_b : bias_a;
    float4 bv = *(const float4*)&bias[t * 4];
    float4 z;
    z.x = acc.x * invd + bv.x;
    z.y = acc.y * invd + bv.y;
    z.z = acc.z * invd + bv.z;
    z.w = acc.w * invd + bv.w;
    z.x = (z.x > 0.0f) ? z.x : (expf(z.x) - 1.0f);
    z.y = (z.y > 0.0f) ? z.y : (expf(z.y) - 1.0f);
    z.z = (z.z > 0.0f) ? z.z : (expf(z.z) - 1.0f);
    z.w = (z.w > 0.0f) ? z.w : (expf(z.w) - 1.0f);
    *(float4*)&g_out[p][d * FF + t * 4] = z;
}

// ---------------- K7: tf32 GEMM  q = Z @ Wsem  + fused tanh.wsem reduce ------
__global__ __launch_bounds__(256) void gemm2_kernel(
    const float* __restrict__ Wsem,
    const float* __restrict__ bsem,
    const float* __restrict__ wsem) {
    __shared__ uint32_t As[GBK][GBM + APAD];
    __shared__ uint32_t Bs[GBK][GBN + BPAD];
    const float* Z = (const float*)g_out;
    const int M = 2 * NN;
    const int tid = threadIdx.x;
    const int lane = tid & 31;
    const int wid = tid >> 5;
    const int mBase = (wid >> 1) * 32;
    const int nBase = (wid & 1) * 32;
    const int rowBase = blockIdx.y * GBM;
    const int colBase = blockIdx.x * GBN;

    float acc[2][4][4];
#pragma unroll
    for (int mf = 0; mf < 2; mf++)
#pragma unroll
        for (int nf = 0; nf < 4; nf++)
#pragma unroll
            for (int c = 0; c < 4; c++) acc[mf][nf][c] = 0.0f;

    for (int k0 = 0; k0 < FF; k0 += GBK) {
#pragma unroll
        for (int it = 0; it < 2; it++) {
            int idx = tid + it * 256;
            int r = idx >> 2, c4 = idx & 3;
            int gr = rowBase + r;
            float4 v = make_float4(0.f, 0.f, 0.f, 0.f);
            if (gr < M) v = *(const float4*)&Z[gr * FF + k0 + c4 * 4];
            As[c4 * 4 + 0][r] = f2tf32(v.x);
            As[c4 * 4 + 1][r] = f2tf32(v.y);
            As[c4 * 4 + 2][r] = f2tf32(v.z);
            As[c4 * 4 + 3][r] = f2tf32(v.w);
        }
        {
            int r = tid >> 4, c4 = tid & 15;
            float4 v = *(const float4*)&Wsem[(k0 + r) * SEM_HID + colBase + c4 * 4];
            Bs[r][c4 * 4 + 0] = f2tf32(v.x);
            Bs[r][c4 * 4 + 1] = f2tf32(v.y);
            Bs[r][c4 * 4 + 2] = f2tf32(v.z);
            Bs[r][c4 * 4 + 3] = f2tf32(v.w);
        }
        __syncthreads();
#pragma unroll
        for (int ks = 0; ks < GBK; ks += 8) {
            uint32_t a[2][4], b[4][2];
#pragma unroll
            for (int mf = 0; mf < 2; mf++) {
                int row = mBase + mf * 16 + (lane >> 2);
                a[mf][0] = As[ks + (lane & 3)][row];
                a[mf][1] = As[ks + (lane & 3)][row + 8];
                a[mf][2] = As[ks + 4 + (lane & 3)][row];
                a[mf][3] = As[ks + 4 + (lane & 3)][row + 8];
            }
#pragma unroll
            for (int nf = 0; nf < 4; nf++) {
                int col = nBase + nf * 8 + (lane >> 2);
                b[nf][0] = Bs[ks + (lane & 3)][col];
                b[nf][1] = Bs[ks + 4 + (lane & 3)][col];
            }
#pragma unroll
            for (int mf = 0; mf < 2; mf++)
#pragma unroll
                for (int nf = 0; nf < 4; nf++)
                    mma_tf32(acc[mf][nf], a[mf][0], a[mf][1], a[mf][2], a[mf][3],
                             b[nf][0], b[nf][1]);
        }
        __syncthreads();
    }

    // ---- epilogue: tanh(q + bsem) . wsem, reduce, atomic into g_qsum --------
    float bsv[8], wsv[8];
#pragma unroll
    for (int nf = 0; nf < 4; nf++) {
        int gc = colBase + nBase + nf * 8 + 2 * (lane & 3);
        bsv[nf * 2 + 0] = bsem[gc];
        bsv[nf * 2 + 1] = bsem[gc + 1];
        wsv[nf * 2 + 0] = wsem[gc];
        wsv[nf * 2 + 1] = wsem[gc + 1];
    }
    float sp0 = 0.0f, sp1 = 0.0f;
#pragma unroll
    for (int mf = 0; mf < 2; mf++) {
#pragma unroll
        for (int half = 0; half < 2; half++) {
            int gr = rowBase + mBase + mf * 16 + half * 8 + (lane >> 2);
            if (gr < M) {
                float rs = 0.0f;
#pragma unroll
                for (int nf = 0; nf < 4; nf++) {
                    rs += tanh_fast(acc[mf][nf][half * 2 + 0] + bsv[nf * 2 + 0]) * wsv[nf * 2 + 0];
                    rs += tanh_fast(acc[mf][nf][half * 2 + 1] + bsv[nf * 2 + 1]) * wsv[nf * 2 + 1];
                }
                if (gr < NN) sp0 += rs; else sp1 += rs;
            }
        }
    }
#pragma unroll
    for (int o = 16; o > 0; o >>= 1) {
        sp0 += __shfl_down_sync(0xffffffffu, sp0, o);
        sp1 += __shfl_down_sync(0xffffffffu, sp1, o);
    }
    __shared__ float sh[8][2];
    if (lane == 0) { sh[wid][0] = sp0; sh[wid][1] = sp1; }
    __syncthreads();
    if (tid == 0) {
        float s0 = 0.f, s1 = 0.f;
#pragma unroll
        for (int k = 0; k < 8; k++) { s0 += sh[k][0]; s1 += sh[k][1]; }
        if (s0 != 0.0f) atomicAdd(&g_qsum[0], s0);
        if (s1 != 0.0f) atomicAdd(&g_qsum[1], s1);
    }
}

// ---------------- K9: combine with semantic softmax --------------------------
__global__ void combine_kernel(float* __restrict__ out) {
    int i = blockIdx.x * blockDim.x + threadIdx.x;
    if (i >= NN * FF) return;
    float q0 = g_qsum[0] * (1.0f / NN);
    float q1 = g_qsum[1] * (1.0f / NN);
    float mx = fmaxf(q0, q1);
    float b0 = __expf(q0 - mx);
    float b1 = __expf(q1 - mx);
    float inv = 1.0f / (b0 + b1);
    out[i] = (g_out[0][i] * b0 + g_out[1][i] * b1) * inv;
}

// ---------------- launch -----------------------------------------------------
extern "C" void kernel_launch(void* const* d_in, const int* in_sizes, int n_in,
                              void* d_out, int out_size) {
    const float* h      = (const float*)d_in[0];
    const int*   src_a  = (const int*)  d_in[1];
    const int*   dst_a  = (const int*)  d_in[2];
    const int*   src_b  = (const int*)  d_in[3];
    const int*   dst_b  = (const int*)  d_in[4];
    const float* W_a    = (const float*)d_in[5];
    const float* al_a   = (const float*)d_in[6];
    const float* ar_a   = (const float*)d_in[7];
    const float* bias_a = (const float*)d_in[8];
    const float* W_b    = (const float*)d_in[9];
    const float* al_b   = (const float*)d_in[10];
    const float* ar_b   = (const float*)d_in[11];
    const float* bias_b = (const float*)d_in[12];
    const float* Wsem   = (const float*)d_in[13];
    const float* bsem   = (const float*)d_in[14];
    const float* wsem   = (const float*)d_in[15];
    float* out = (float*)d_out;

    (void)in_sizes; (void)n_in; (void)out_size;

    init_kernel<<<(NN + 255) / 256, 256>>>();

    {   // K1: projection GEMM (tf32 TC) + fused el/er
        dim3 grid((2 * FF) / GBN, (NN + GBM - 1) / GBM);
        gemm1_kernel<<<grid, 256>>>(h, W_a, W_b, al_a, ar_a, al_b, ar_b);
    }

    count_kernel<<<(2 * EE + 255) / 256, 256>>>(dst_a, dst_b);

    {   // 3-phase scan
        dim3 grid(NCHUNK, 2);
        reduce_kernel<<<grid, 256>>>();
        bscan_kernel<<<2, 32>>>();
        scanapply_kernel<<<grid, 1024>>>();
    }

    scatter_kernel<<<(2 * EE + 255) / 256, 256>>>(src_a, dst_a, src_b, dst_b);

    {   // gather aggregation + softmax + bias + ELU
        dim3 grid(NN, 2);
        agg_kernel<<<grid, 64>>>(bias_a, bias_b);
    }

    {   // semantic GEMM (tf32 TC) + fused tanh.wsem reduction
        dim3 grid(SEM_HID / GBN, (2 * NN + GBM - 1) / GBM);
        gemm2_kernel<<<grid, 256>>>(Wsem, bsem, wsem);
    }

    combine_kernel<<<(NN * FF + 255) / 256, 256>>>(out);
}

// round 8
// speedup vs baseline: 8.4139x; 1.1016x over previous
#include <cuda_runtime.h>
#include <cuda_fp16.h>
#include <math.h>
#include <stdint.h>

#define NN      50000
#define IN_DIM  128
#define OUT_DIM 32
#define HEADS   8
#define FF      256          // OUT_DIM * HEADS
#define EE      800000
#define SEM_HID 128
#define NCHUNK  49           // ceil(NN / 1024)

// ---------------- scratch (static device globals; no allocation) -------------
__device__ __half g_feat16[2][NN * FF];    // W-projected features (fp16, agg-only)
__device__ float  g_out[2][NN * FF];       // z (bias+ELU applied in agg epilogue)
__device__ float  g_el[2][NN * HEADS];
__device__ float  g_er[2][NN * HEADS];
__device__ int    g_csrc[2][EE];           // CSR src node per slot
__device__ int    g_rowptr[2][NN + 1];
__device__ int    g_cnt[2][NN];            // zero-init at load; re-zeroed by scanapply
__device__ int    g_cursor[2][NN];
__device__ int    g_bsum[2][NCHUNK];
__device__ float  g_qsum[2];               // zero-init at load; re-zeroed by count

// ---------------- tf32 helpers -----------------------------------------------
__device__ __forceinline__ uint32_t f2tf32(float x) {
    uint32_t r;
    asm("cvt.rna.tf32.f32 %0, %1;" : "=r"(r) : "f"(x));
    return r;
}
__device__ __forceinline__ void mma_tf32(float c[4],
                                         uint32_t a0, uint32_t a1, uint32_t a2, uint32_t a3,
                                         uint32_t b0, uint32_t b1) {
    asm volatile(
        "mma.sync.aligned.m16n8k8.row.col.f32.tf32.tf32.f32 "
        "{%0,%1,%2,%3}, {%4,%5,%6,%7}, {%8,%9}, {%0,%1,%2,%3};\n"
        : "+f"(c[0]), "+f"(c[1]), "+f"(c[2]), "+f"(c[3])
        : "r"(a0), "r"(a1), "r"(a2), "r"(a3), "r"(b0), "r"(b1));
}
__device__ __forceinline__ float tanh_fast(float x) {
    float r;
    asm("tanh.approx.f32 %0, %1;" : "=f"(r) : "f"(x));
    return r;
}

// ---------------- K1: tf32 GEMM  feat = h @ [W_a|W_b]  + fused el/er ---------
#define GBM 128
#define GBN 64
#define GBK 16
#define APAD 8
#define BPAD 8
__global__ __launch_bounds__(256) void gemm1_kernel(
    const float* __restrict__ h,
    const float* __restrict__ Wa,
    const float* __restrict__ Wb,
    const float* __restrict__ al_a,
    const float* __restrict__ ar_a,
    const float* __restrict__ al_b,
    const float* __restrict__ ar_b) {
    __shared__ uint32_t As[GBK][GBM + APAD];
    __shared__ uint32_t Bs[GBK][GBN + BPAD];
    const int tid = threadIdx.x;
    const int lane = tid & 31;
    const int wid = tid >> 5;
    const int mBase = (wid >> 1) * 32;
    const int nBase = (wid & 1) * 32;
    const int rowBase = blockIdx.y * GBM;
    const int colBase = blockIdx.x * GBN;

    float acc[2][4][4];
#pragma unroll
    for (int mf = 0; mf < 2; mf++)
#pragma unroll
        for (int nf = 0; nf < 4; nf++)
#pragma unroll
            for (int c = 0; c < 4; c++) acc[mf][nf][c] = 0.0f;

    for (int k0 = 0; k0 < IN_DIM; k0 += GBK) {
#pragma unroll
        for (int it = 0; it < 2; it++) {
            int idx = tid + it * 256;
            int r = idx >> 2, c4 = idx & 3;
            int gr = rowBase + r;
            float4 v = make_float4(0.f, 0.f, 0.f, 0.f);
            if (gr < NN) v = *(const float4*)&h[gr * IN_DIM + k0 + c4 * 4];
            As[c4 * 4 + 0][r] = f2tf32(v.x);
            As[c4 * 4 + 1][r] = f2tf32(v.y);
            As[c4 * 4 + 2][r] = f2tf32(v.z);
            As[c4 * 4 + 3][r] = f2tf32(v.w);
        }
        {
            int r = tid >> 4, c4 = tid & 15;
            int gc = colBase + c4 * 4;
            const float* W = (gc >= FF) ? Wb : Wa;
            int cc = gc & (FF - 1);
            float4 v = *(const float4*)&W[(k0 + r) * FF + cc];
            Bs[r][c4 * 4 + 0] = f2tf32(v.x);
            Bs[r][c4 * 4 + 1] = f2tf32(v.y);
            Bs[r][c4 * 4 + 2] = f2tf32(v.z);
            Bs[r][c4 * 4 + 3] = f2tf32(v.w);
        }
        __syncthreads();
#pragma unroll
        for (int ks = 0; ks < GBK; ks += 8) {
            uint32_t a[2][4], b[4][2];
#pragma unroll
            for (int mf = 0; mf < 2; mf++) {
                int row = mBase + mf * 16 + (lane >> 2);
                a[mf][0] = As[ks + (lane & 3)][row];
                a[mf][1] = As[ks + (lane & 3)][row + 8];
                a[mf][2] = As[ks + 4 + (lane & 3)][row];
                a[mf][3] = As[ks + 4 + (lane & 3)][row + 8];
            }
#pragma unroll
            for (int nf = 0; nf < 4; nf++) {
                int col = nBase + nf * 8 + (lane >> 2);
                b[nf][0] = Bs[ks + (lane & 3)][col];
                b[nf][1] = Bs[ks + 4 + (lane & 3)][col];
            }
#pragma unroll
            for (int mf = 0; mf < 2; mf++)
#pragma unroll
                for (int nf = 0; nf < 4; nf++)
                    mma_tf32(acc[mf][nf], a[mf][0], a[mf][1], a[mf][2], a[mf][3],
                             b[nf][0], b[nf][1]);
        }
        __syncthreads();
    }

    // ---- epilogue: write feat (fp16) + fused el/er (warp N-span == one head)
    const int gc0 = colBase + nBase;          // 32-aligned
    const int hg = gc0 >> 5;                  // global head 0..15
    const int p = hg >> 3;
    const int hd = hg & 7;
    const float* al = p ? al_b : al_a;
    const float* ar = p ? ar_b : ar_a;
    float alv[8], arv[8];
#pragma unroll
    for (int nf = 0; nf < 4; nf++) {
        int c = nf * 8 + 2 * (lane & 3);
        alv[nf * 2 + 0] = al[hd * OUT_DIM + c];
        alv[nf * 2 + 1] = al[hd * OUT_DIM + c + 1];
        arv[nf * 2 + 0] = ar[hd * OUT_DIM + c];
        arv[nf * 2 + 1] = ar[hd * OUT_DIM + c + 1];
    }
    const int ccBase = gc0 & 255;
#pragma unroll
    for (int mf = 0; mf < 2; mf++) {
#pragma unroll
        for (int half = 0; half < 2; half++) {
            int gr = rowBase + mBase + mf * 16 + half * 8 + (lane >> 2);
            float el = 0.0f, er = 0.0f;
            if (gr < NN) {
#pragma unroll
                for (int nf = 0; nf < 4; nf++) {
                    float v0 = acc[mf][nf][half * 2 + 0];
                    float v1 = acc[mf][nf][half * 2 + 1];
                    int cc = ccBase + nf * 8 + 2 * (lane & 3);
                    *(__half2*)&g_feat16[p][gr * FF + cc] = __floats2half2_rn(v0, v1);
                    el += v0 * alv[nf * 2] + v1 * alv[nf * 2 + 1];
                    er += v0 * arv[nf * 2] + v1 * arv[nf * 2 + 1];
                }
            }
            el += __shfl_xor_sync(0xffffffffu, el, 1);
            el += __shfl_xor_sync(0xffffffffu, el, 2);
            er += __shfl_xor_sync(0xffffffffu, er, 1);
            er += __shfl_xor_sync(0xffffffffu, er, 2);
            if ((lane & 3) == 0 && gr < NN) {
                g_el[p][gr * HEADS + hd] = el;
                g_er[p][gr * HEADS + hd] = er;
            }
        }
    }
}

// ---------------- K3: degree histogram (+ qsum reset) ------------------------
__global__ void count_kernel(const int* __restrict__ dst_a,
                             const int* __restrict__ dst_b) {
    int i = blockIdx.x * blockDim.x + threadIdx.x;
    if (i < 2) g_qsum[i] = 0.0f;          // reset for this replay (precedes gemm2)
    if (i >= 2 * EE) return;
    int p = (i >= EE) ? 1 : 0;
    int e = i - p * EE;
    int d = p ? dst_b[e] : dst_a[e];
    atomicAdd(&g_cnt[p][d], 1);
}

// ---------------- K4a: per-chunk reduce --------------------------------------
__global__ __launch_bounds__(256) void reduce_kernel() {
    int p = blockIdx.y, c = blockIdx.x, t = threadIdx.x;
    int base = c * 1024;
    int v = 0;
#pragma unroll
    for (int k = 0; k < 4; k++) {
        int i = base + t + k * 256;
        if (i < NN) v += g_cnt[p][i];
    }
    __shared__ int sh[256];
    sh[t] = v;
    __syncthreads();
#pragma unroll
    for (int st = 128; st > 0; st >>= 1) {
        if (t < st) sh[t] += sh[t + st];
        __syncthreads();
    }
    if (t == 0) g_bsum[p][c] = sh[0];
}

// ---------------- K4b: tiny serial scan of chunk sums ------------------------
__global__ void bscan_kernel() {
    int p = blockIdx.x;
    if (threadIdx.x != 0) return;
    int run = 0;
    for (int c = 0; c < NCHUNK; c++) {
        int tmp = g_bsum[p][c];
        g_bsum[p][c] = run;
        run += tmp;
    }
}

// ---------------- K4c: scan apply -> rowptr + cursor (+ cnt reset) -----------
__global__ __launch_bounds__(1024) void scanapply_kernel() {
    int p = blockIdx.y, c = blockIdx.x, t = threadIdx.x;
    int i = c * 1024 + t;
    int v = (i < NN) ? g_cnt[p][i] : 0;
    int lane = t & 31, w = t >> 5;
    int x = v;
#pragma unroll
    for (int o = 1; o < 32; o <<= 1) {
        int y = __shfl_up_sync(0xffffffffu, x, o);
        if (lane >= o) x += y;
    }
    __shared__ int ws[32];
    if (lane == 31) ws[w] = x;
    __syncthreads();
    if (w == 0) {
        int y = ws[lane];
#pragma unroll
        for (int o = 1; o < 32; o <<= 1) {
            int z = __shfl_up_sync(0xffffffffu, y, o);
            if (lane >= o) y += z;
        }
        ws[lane] = y;
    }
    __syncthreads();
    int incl = x + ((w > 0) ? ws[w - 1] : 0) + g_bsum[p][c];
    if (i < NN) {
        g_rowptr[p][i + 1] = incl;
        g_cursor[p][i]     = incl - v;
        g_cnt[p][i]        = 0;           // reset for next replay
    }
    if (i == 0) g_rowptr[p][0] = 0;
}

// ---------------- K5: scatter into CSR (slim: cursor + csrc only) ------------
__global__ void scatter_kernel(const int* __restrict__ src_a,
                               const int* __restrict__ dst_a,
                               const int* __restrict__ src_b,
                               const int* __restrict__ dst_b) {
    int i = blockIdx.x * blockDim.x + threadIdx.x;
    if (i >= 2 * EE) return;
    int p = (i >= EE) ? 1 : 0;
    int e = i - p * EE;
    int s = p ? src_b[e] : src_a[e];
    int d = p ? dst_b[e] : dst_a[e];
    int pos = atomicAdd(&g_cursor[p][d], 1);
    g_csrc[p][pos] = s;
}

// ---------------- K6: per-dst aggregation + softmax + bias + ELU -------------
// 128 threads per block; 2 dsts per block; 64 threads per (dst, metapath).
__global__ __launch_bounds__(128) void agg_kernel(const float* __restrict__ bias_a,
                                                  const float* __restrict__ bias_b) {
    const int d = blockIdx.x * 2 + (threadIdx.x >> 6);
    const int p = blockIdx.y;
    const int t = threadIdx.x & 63;          // 0..63
    const int start = g_rowptr[p][d];
    const int end   = g_rowptr[p][d + 1];
    const int hd = t >> 3;                   // head for cols [t*4, t*4+4)

    const float er = __ldg(&g_er[p][d * HEADS + hd]);
    const __half* fbase = &g_feat16[p][0];
    const float*  elbase = &g_el[p][0];
    const int*    csrc   = &g_csrc[p][0];

    float4 acc = make_float4(0.f, 0.f, 0.f, 0.f);
    float den = 0.0f;

    int j = start;
    for (; j + 1 < end; j += 2) {
        int s0 = csrc[j];
        int s1 = csrc[j + 1];
        float el0 = __ldg(&elbase[s0 * HEADS + hd]);
        float el1 = __ldg(&elbase[s1 * HEADS + hd]);
        uint2 r0 = *(const uint2*)&fbase[s0 * FF + t * 4];
        uint2 r1 = *(const uint2*)&fbase[s1 * FF + t * 4];
        float x0 = el0 + er; x0 = (x0 > 0.0f) ? x0 : 0.2f * x0;
        float x1 = el1 + er; x1 = (x1 > 0.0f) ? x1 : 0.2f * x1;
        float ex0 = __expf(x0);
        float ex1 = __expf(x1);
        den += ex0 + ex1;
        float2 a0 = __half22float2(*(const __half2*)&r0.x);
        float2 b0 = __half22float2(*(const __half2*)&r0.y);
        float2 a1 = __half22float2(*(const __half2*)&r1.x);
        float2 b1 = __half22float2(*(const __half2*)&r1.y);
        acc.x += a0.x * ex0 + a1.x * ex1;
        acc.y += a0.y * ex0 + a1.y * ex1;
        acc.z += b0.x * ex0 + b1.x * ex1;
        acc.w += b0.y * ex0 + b1.y * ex1;
    }
    if (j < end) {
        int s0 = csrc[j];
        float el0 = __ldg(&elbase[s0 * HEADS + hd]);
        uint2 r0 = *(const uint2*)&fbase[s0 * FF + t * 4];
        float x0 = el0 + er; x0 = (x0 > 0.0f) ? x0 : 0.2f * x0;
        float ex0 = __expf(x0);
        den += ex0;
        float2 a0 = __half22float2(*(const __half2*)&r0.x);
        float2 b0 = __half22float2(*(const __half2*)&r0.y);
        acc.x += a0.x * ex0;
        acc.y += a0.y * ex0;
        acc.z += b0.x * ex0;
        acc.w += b0.y * ex0;
    }

    float invd = (den > 0.0f) ? 1.0f / den : 1.0f;
    const float* bias = p ? bias_b : bias_a;
    float4 bv = *(const float4*)&bias[t * 4];
    float4 z;
    z.x = acc.x * invd + bv.x;
    z.y = acc.y * invd + bv.y;
    z.z = acc.z * invd + bv.z;
    z.w = acc.w * invd + bv.w;
    z.x = (z.x > 0.0f) ? z.x : (expf(z.x) - 1.0f);
    z.y = (z.y > 0.0f) ? z.y : (expf(z.y) - 1.0f);
    z.z = (z.z > 0.0f) ? z.z : (expf(z.z) - 1.0f);
    z.w = (z.w > 0.0f) ? z.w : (expf(z.w) - 1.0f);
    *(float4*)&g_out[p][d * FF + t * 4] = z;
}

// ---------------- K7: tf32 GEMM  q = Z @ Wsem  + fused tanh.wsem reduce ------
__global__ __launch_bounds__(256) void gemm2_kernel(
    const float* __restrict__ Wsem,
    const float* __restrict__ bsem,
    const float* __restrict__ wsem) {
    __shared__ uint32_t As[GBK][GBM + APAD];
    __shared__ uint32_t Bs[GBK][GBN + BPAD];
    const float* Z = (const float*)g_out;
    const int M = 2 * NN;
    const int tid = threadIdx.x;
    const int lane = tid & 31;
    const int wid = tid >> 5;
    const int mBase = (wid >> 1) * 32;
    const int nBase = (wid & 1) * 32;
    const int rowBase = blockIdx.y * GBM;
    const int colBase = blockIdx.x * GBN;

    float acc[2][4][4];
#pragma unroll
    for (int mf = 0; mf < 2; mf++)
#pragma unroll
        for (int nf = 0; nf < 4; nf++)
#pragma unroll
            for (int c = 0; c < 4; c++) acc[mf][nf][c] = 0.0f;

    for (int k0 = 0; k0 < FF; k0 += GBK) {
#pragma unroll
        for (int it = 0; it < 2; it++) {
            int idx = tid + it * 256;
            int r = idx >> 2, c4 = idx & 3;
            int gr = rowBase + r;
            float4 v = make_float4(0.f, 0.f, 0.f, 0.f);
            if (gr < M) v = *(const float4*)&Z[gr * FF + k0 + c4 * 4];
            As[c4 * 4 + 0][r] = f2tf32(v.x);
            As[c4 * 4 + 1][r] = f2tf32(v.y);
            As[c4 * 4 + 2][r] = f2tf32(v.z);
            As[c4 * 4 + 3][r] = f2tf32(v.w);
        }
        {
            int r = tid >> 4, c4 = tid & 15;
            float4 v = *(const float4*)&Wsem[(k0 + r) * SEM_HID + colBase + c4 * 4];
            Bs[r][c4 * 4 + 0] = f2tf32(v.x);
            Bs[r][c4 * 4 + 1] = f2tf32(v.y);
            Bs[r][c4 * 4 + 2] = f2tf32(v.z);
            Bs[r][c4 * 4 + 3] = f2tf32(v.w);
        }
        __syncthreads();
#pragma unroll
        for (int ks = 0; ks < GBK; ks += 8) {
            uint32_t a[2][4], b[4][2];
#pragma unroll
            for (int mf = 0; mf < 2; mf++) {
                int row = mBase + mf * 16 + (lane >> 2);
                a[mf][0] = As[ks + (lane & 3)][row];
                a[mf][1] = As[ks + (lane & 3)][row + 8];
                a[mf][2] = As[ks + 4 + (lane & 3)][row];
                a[mf][3] = As[ks + 4 + (lane & 3)][row + 8];
            }
#pragma unroll
            for (int nf = 0; nf < 4; nf++) {
                int col = nBase + nf * 8 + (lane >> 2);
                b[nf][0] = Bs[ks + (lane & 3)][col];
                b[nf][1] = Bs[ks + 4 + (lane & 3)][col];
            }
#pragma unroll
            for (int mf = 0; mf < 2; mf++)
#pragma unroll
                for (int nf = 0; nf < 4; nf++)
                    mma_tf32(acc[mf][nf], a[mf][0], a[mf][1], a[mf][2], a[mf][3],
                             b[nf][0], b[nf][1]);
        }
        __syncthreads();
    }

    // ---- epilogue: tanh(q + bsem) . wsem, reduce, atomic into g_qsum --------
    float bsv[8], wsv[8];
#pragma unroll
    for (int nf = 0; nf < 4; nf++) {
        int gc = colBase + nBase + nf * 8 + 2 * (lane & 3);
        bsv[nf * 2 + 0] = bsem[gc];
        bsv[nf * 2 + 1] = bsem[gc + 1];
        wsv[nf * 2 + 0] = wsem[gc];
        wsv[nf * 2 + 1] = wsem[gc + 1];
    }
    float sp0 = 0.0f, sp1 = 0.0f;
#pragma unroll
    for (int mf = 0; mf < 2; mf++) {
#pragma unroll
        for (int half = 0; half < 2; half++) {
            int gr = rowBase + mBase + mf * 16 + half * 8 + (lane >> 2);
            if (gr < M) {
                float rs = 0.0f;
#pragma unroll
                for (int nf = 0; nf < 4; nf++) {
                    rs += tanh_fast(acc[mf][nf][half * 2 + 0] + bsv[nf * 2 + 0]) * wsv[nf * 2 + 0];
                    rs += tanh_fast(acc[mf][nf][half * 2 + 1] + bsv[nf * 2 + 1]) * wsv[nf * 2 + 1];
                }
                if (gr < NN) sp0 += rs; else sp1 += rs;
            }
        }
    }
#pragma unroll
    for (int o = 16; o > 0; o >>= 1) {
        sp0 += __shfl_down_sync(0xffffffffu, sp0, o);
        sp1 += __shfl_down_sync(0xffffffffu, sp1, o);
    }
    __shared__ float sh[8][2];
    if (lane == 0) { sh[wid][0] = sp0; sh[wid][1] = sp1; }
    __syncthreads();
    if (tid == 0) {
        float s0 = 0.f, s1 = 0.f;
#pragma unroll
        for (int k = 0; k < 8; k++) { s0 += sh[k][0]; s1 += sh[k][1]; }
        if (s0 != 0.0f) atomicAdd(&g_qsum[0], s0);
        if (s1 != 0.0f) atomicAdd(&g_qsum[1], s1);
    }
}

// ---------------- K9: combine with semantic softmax (float4) -----------------
__global__ void combine_kernel(float4* __restrict__ out) {
    int i = blockIdx.x * blockDim.x + threadIdx.x;
    if (i >= NN * FF / 4) return;
    float q0 = g_qsum[0] * (1.0f / NN);
    float q1 = g_qsum[1] * (1.0f / NN);
    float mx = fmaxf(q0, q1);
    float b0 = __expf(q0 - mx);
    float b1 = __expf(q1 - mx);
    float inv = 1.0f / (b0 + b1);
    b0 *= inv; b1 *= inv;
    float4 z0 = *(const float4*)&g_out[0][i * 4];
    float4 z1 = *(const float4*)&g_out[1][i * 4];
    float4 r;
    r.x = z0.x * b0 + z1.x * b1;
    r.y = z0.y * b0 + z1.y * b1;
    r.z = z0.z * b0 + z1.z * b1;
    r.w = z0.w * b0 + z1.w * b1;
    out[i] = r;
}

// ---------------- launch -----------------------------------------------------
extern "C" void kernel_launch(void* const* d_in, const int* in_sizes, int n_in,
                              void* d_out, int out_size) {
    const float* h      = (const float*)d_in[0];
    const int*   src_a  = (const int*)  d_in[1];
    const int*   dst_a  = (const int*)  d_in[2];
    const int*   src_b  = (const int*)  d_in[3];
    const int*   dst_b  = (const int*)  d_in[4];
    const float* W_a    = (const float*)d_in[5];
    const float* al_a   = (const float*)d_in[6];
    const float* ar_a   = (const float*)d_in[7];
    const float* bias_a = (const float*)d_in[8];
    const float* W_b    = (const float*)d_in[9];
    const float* al_b   = (const float*)d_in[10];
    const float* ar_b   = (const float*)d_in[11];
    const float* bias_b = (const float*)d_in[12];
    const float* Wsem   = (const float*)d_in[13];
    const float* bsem   = (const float*)d_in[14];
    const float* wsem   = (const float*)d_in[15];
    float* out = (float*)d_out;

    (void)in_sizes; (void)n_in; (void)out_size;

    // One-time creation of side stream + events (host objects, no device mem).
    static cudaStream_t s2 = nullptr;
    static cudaEvent_t ev_fork = nullptr, ev_join = nullptr;
    if (s2 == nullptr) {
        cudaStreamCreateWithFlags(&s2, cudaStreamNonBlocking);
        cudaEventCreateWithFlags(&ev_fork, cudaEventDisableTiming);
        cudaEventCreateWithFlags(&ev_join, cudaEventDisableTiming);
    }

    // ---- fork: CSR build on s2, projection GEMM on main stream --------------
    cudaEventRecord(ev_fork, 0);
    cudaStreamWaitEvent(s2, ev_fork, 0);

    // s2 branch: count -> scan -> scatter (depends only on edge lists)
    count_kernel<<<(2 * EE + 255) / 256, 256, 0, s2>>>(dst_a, dst_b);
    {
        dim3 grid(NCHUNK, 2);
        reduce_kernel<<<grid, 256, 0, s2>>>();
        bscan_kernel<<<2, 32, 0, s2>>>();
        scanapply_kernel<<<grid, 1024, 0, s2>>>();
    }
    scatter_kernel<<<(2 * EE + 255) / 256, 256, 0, s2>>>(src_a, dst_a, src_b, dst_b);
    cudaEventRecord(ev_join, s2);

    // main branch: projection GEMM (tf32 TC) + fused el/er
    {
        dim3 grid((2 * FF) / GBN, (NN + GBM - 1) / GBM);
        gemm1_kernel<<<grid, 256>>>(h, W_a, W_b, al_a, ar_a, al_b, ar_b);
    }

    // ---- join ----------------------------------------------------------------
    cudaStreamWaitEvent(0, ev_join, 0);

    {   // gather aggregation + softmax + bias + ELU (2 dsts per block)
        dim3 grid(NN / 2, 2);
        agg_kernel<<<grid, 128>>>(bias_a, bias_b);
    }

    {   // semantic GEMM (tf32 TC) + fused tanh.wsem reduction
        dim3 grid(SEM_HID / GBN, (2 * NN + GBM - 1) / GBM);
        gemm2_kernel<<<grid, 256>>>(Wsem, bsem, wsem);
    }

    combine_kernel<<<(NN * FF / 4 + 255) / 256, 256>>>((float4*)out);
}

// round 9
// speedup vs baseline: 9.2574x; 1.1002x over previous
#include <cuda_runtime.h>
#include <cuda_fp16.h>
#include <math.h>
#include <stdint.h>

#define NN      50000
#define IN_DIM  128
#define OUT_DIM 32
#define HEADS   8
#define FF      256          // OUT_DIM * HEADS
#define EE      800000
#define SEM_HID 128
#define NCHUNK  49           // ceil(NN / 1024)

// ---------------- scratch (static device globals; no allocation) -------------
__device__ __half g_feat16[2][NN * FF];    // W-projected features (fp16, agg-only)
__device__ __half g_z16[2][NN * FF];       // z (fp16) = ELU(agg + bias)
__device__ float  g_el[2][NN * HEADS];
__device__ float  g_er[2][NN * HEADS];
__device__ int    g_csrc[2][EE];           // CSR src node per slot
__device__ int    g_rowptr[2][NN + 1];
__device__ int    g_cnt[2][NN];            // zero-init at load; re-zeroed by scanapply
__device__ int    g_cursor[2][NN];
__device__ int    g_bsum[2][NCHUNK];
__device__ float  g_qsum[2];               // zero-init at load; re-zeroed by count

// ---------------- mma helpers -------------------------------------------------
__device__ __forceinline__ uint32_t f2tf32(float x) {
    uint32_t r;
    asm("cvt.rna.tf32.f32 %0, %1;" : "=r"(r) : "f"(x));
    return r;
}
__device__ __forceinline__ void mma_tf32(float c[4],
                                         uint32_t a0, uint32_t a1, uint32_t a2, uint32_t a3,
                                         uint32_t b0, uint32_t b1) {
    asm volatile(
        "mma.sync.aligned.m16n8k8.row.col.f32.tf32.tf32.f32 "
        "{%0,%1,%2,%3}, {%4,%5,%6,%7}, {%8,%9}, {%0,%1,%2,%3};\n"
        : "+f"(c[0]), "+f"(c[1]), "+f"(c[2]), "+f"(c[3])
        : "r"(a0), "r"(a1), "r"(a2), "r"(a3), "r"(b0), "r"(b1));
}
__device__ __forceinline__ void mma_f16(float c[4],
                                        uint32_t a0, uint32_t a1, uint32_t a2, uint32_t a3,
                                        uint32_t b0, uint32_t b1) {
    asm volatile(
        "mma.sync.aligned.m16n8k16.row.col.f32.f16.f16.f32 "
        "{%0,%1,%2,%3}, {%4,%5,%6,%7}, {%8,%9}, {%0,%1,%2,%3};\n"
        : "+f"(c[0]), "+f"(c[1]), "+f"(c[2]), "+f"(c[3])
        : "r"(a0), "r"(a1), "r"(a2), "r"(a3), "r"(b0), "r"(b1));
}
__device__ __forceinline__ float tanh_fast(float x) {
    float r;
    asm("tanh.approx.f32 %0, %1;" : "=f"(r) : "f"(x));
    return r;
}

// ---------------- K1: tf32 GEMM  feat = h @ [W_a|W_b]  + fused el/er ---------
#define GBM 128
#define GBN 64
#define GBK 16
#define APAD 8
#define BPAD 8
__global__ __launch_bounds__(256) void gemm1_kernel(
    const float* __restrict__ h,
    const float* __restrict__ Wa,
    const float* __restrict__ Wb,
    const float* __restrict__ al_a,
    const float* __restrict__ ar_a,
    const float* __restrict__ al_b,
    const float* __restrict__ ar_b) {
    __shared__ uint32_t As[GBK][GBM + APAD];
    __shared__ uint32_t Bs[GBK][GBN + BPAD];
    const int tid = threadIdx.x;
    const int lane = tid & 31;
    const int wid = tid >> 5;
    const int mBase = (wid >> 1) * 32;
    const int nBase = (wid & 1) * 32;
    const int rowBase = blockIdx.y * GBM;
    const int colBase = blockIdx.x * GBN;

    float acc[2][4][4];
#pragma unroll
    for (int mf = 0; mf < 2; mf++)
#pragma unroll
        for (int nf = 0; nf < 4; nf++)
#pragma unroll
            for (int c = 0; c < 4; c++) acc[mf][nf][c] = 0.0f;

    for (int k0 = 0; k0 < IN_DIM; k0 += GBK) {
#pragma unroll
        for (int it = 0; it < 2; it++) {
            int idx = tid + it * 256;
            int r = idx >> 2, c4 = idx & 3;
            int gr = rowBase + r;
            float4 v = make_float4(0.f, 0.f, 0.f, 0.f);
            if (gr < NN) v = *(const float4*)&h[gr * IN_DIM + k0 + c4 * 4];
            As[c4 * 4 + 0][r] = f2tf32(v.x);
            As[c4 * 4 + 1][r] = f2tf32(v.y);
            As[c4 * 4 + 2][r] = f2tf32(v.z);
            As[c4 * 4 + 3][r] = f2tf32(v.w);
        }
        {
            int r = tid >> 4, c4 = tid & 15;
            int gc = colBase + c4 * 4;
            const float* W = (gc >= FF) ? Wb : Wa;
            int cc = gc & (FF - 1);
            float4 v = *(const float4*)&W[(k0 + r) * FF + cc];
            Bs[r][c4 * 4 + 0] = f2tf32(v.x);
            Bs[r][c4 * 4 + 1] = f2tf32(v.y);
            Bs[r][c4 * 4 + 2] = f2tf32(v.z);
            Bs[r][c4 * 4 + 3] = f2tf32(v.w);
        }
        __syncthreads();
#pragma unroll
        for (int ks = 0; ks < GBK; ks += 8) {
            uint32_t a[2][4], b[4][2];
#pragma unroll
            for (int mf = 0; mf < 2; mf++) {
                int row = mBase + mf * 16 + (lane >> 2);
                a[mf][0] = As[ks + (lane & 3)][row];
                a[mf][1] = As[ks + (lane & 3)][row + 8];
                a[mf][2] = As[ks + 4 + (lane & 3)][row];
                a[mf][3] = As[ks + 4 + (lane & 3)][row + 8];
            }
#pragma unroll
            for (int nf = 0; nf < 4; nf++) {
                int col = nBase + nf * 8 + (lane >> 2);
                b[nf][0] = Bs[ks + (lane & 3)][col];
                b[nf][1] = Bs[ks + 4 + (lane & 3)][col];
            }
#pragma unroll
            for (int mf = 0; mf < 2; mf++)
#pragma unroll
                for (int nf = 0; nf < 4; nf++)
                    mma_tf32(acc[mf][nf], a[mf][0], a[mf][1], a[mf][2], a[mf][3],
                             b[nf][0], b[nf][1]);
        }
        __syncthreads();
    }

    // ---- epilogue: write feat (fp16) + fused el/er (warp N-span == one head)
    const int gc0 = colBase + nBase;          // 32-aligned
    const int hg = gc0 >> 5;                  // global head 0..15
    const int p = hg >> 3;
    const int hd = hg & 7;
    const float* al = p ? al_b : al_a;
    const float* ar = p ? ar_b : ar_a;
    float alv[8], arv[8];
#pragma unroll
    for (int nf = 0; nf < 4; nf++) {
        int c = nf * 8 + 2 * (lane & 3);
        alv[nf * 2 + 0] = al[hd * OUT_DIM + c];
        alv[nf * 2 + 1] = al[hd * OUT_DIM + c + 1];
        arv[nf * 2 + 0] = ar[hd * OUT_DIM + c];
        arv[nf * 2 + 1] = ar[hd * OUT_DIM + c + 1];
    }
    const int ccBase = gc0 & 255;
#pragma unroll
    for (int mf = 0; mf < 2; mf++) {
#pragma unroll
        for (int half = 0; half < 2; half++) {
            int gr = rowBase + mBase + mf * 16 + half * 8 + (lane >> 2);
            float el = 0.0f, er = 0.0f;
            if (gr < NN) {
#pragma unroll
                for (int nf = 0; nf < 4; nf++) {
                    float v0 = acc[mf][nf][half * 2 + 0];
                    float v1 = acc[mf][nf][half * 2 + 1];
                    int cc = ccBase + nf * 8 + 2 * (lane & 3);
                    *(__half2*)&g_feat16[p][gr * FF + cc] = __floats2half2_rn(v0, v1);
                    el += v0 * alv[nf * 2] + v1 * alv[nf * 2 + 1];
                    er += v0 * arv[nf * 2] + v1 * arv[nf * 2 + 1];
                }
            }
            el += __shfl_xor_sync(0xffffffffu, el, 1);
            el += __shfl_xor_sync(0xffffffffu, el, 2);
            er += __shfl_xor_sync(0xffffffffu, er, 1);
            er += __shfl_xor_sync(0xffffffffu, er, 2);
            if ((lane & 3) == 0 && gr < NN) {
                g_el[p][gr * HEADS + hd] = el;
                g_er[p][gr * HEADS + hd] = er;
            }
        }
    }
}

// ---------------- K3: degree histogram (+ qsum reset) ------------------------
__global__ void count_kernel(const int* __restrict__ dst_a,
                             const int* __restrict__ dst_b) {
    int i = blockIdx.x * blockDim.x + threadIdx.x;
    if (i < 2) g_qsum[i] = 0.0f;          // reset for this replay (precedes gemm2)
    if (i >= 2 * EE) return;
    int p = (i >= EE) ? 1 : 0;
    int e = i - p * EE;
    int d = p ? dst_b[e] : dst_a[e];
    atomicAdd(&g_cnt[p][d], 1);
}

// ---------------- K4a: per-chunk reduce --------------------------------------
__global__ __launch_bounds__(256) void reduce_kernel() {
    int p = blockIdx.y, c = blockIdx.x, t = threadIdx.x;
    int base = c * 1024;
    int v = 0;
#pragma unroll
    for (int k = 0; k < 4; k++) {
        int i = base + t + k * 256;
        if (i < NN) v += g_cnt[p][i];
    }
    __shared__ int sh[256];
    sh[t] = v;
    __syncthreads();
#pragma unroll
    for (int st = 128; st > 0; st >>= 1) {
        if (t < st) sh[t] += sh[t + st];
        __syncthreads();
    }
    if (t == 0) g_bsum[p][c] = sh[0];
}

// ---------------- K4b: tiny serial scan of chunk sums ------------------------
__global__ void bscan_kernel() {
    int p = blockIdx.x;
    if (threadIdx.x != 0) return;
    int run = 0;
    for (int c = 0; c < NCHUNK; c++) {
        int tmp = g_bsum[p][c];
        g_bsum[p][c] = run;
        run += tmp;
    }
}

// ---------------- K4c: scan apply -> rowptr + cursor (+ cnt reset) -----------
__global__ __launch_bounds__(1024) void scanapply_kernel() {
    int p = blockIdx.y, c = blockIdx.x, t = threadIdx.x;
    int i = c * 1024 + t;
    int v = (i < NN) ? g_cnt[p][i] : 0;
    int lane = t & 31, w = t >> 5;
    int x = v;
#pragma unroll
    for (int o = 1; o < 32; o <<= 1) {
        int y = __shfl_up_sync(0xffffffffu, x, o);
        if (lane >= o) x += y;
    }
    __shared__ int ws[32];
    if (lane == 31) ws[w] = x;
    __syncthreads();
    if (w == 0) {
        int y = ws[lane];
#pragma unroll
        for (int o = 1; o < 32; o <<= 1) {
            int z = __shfl_up_sync(0xffffffffu, y, o);
            if (lane >= o) y += z;
        }
        ws[lane] = y;
    }
    __syncthreads();
    int incl = x + ((w > 0) ? ws[w - 1] : 0) + g_bsum[p][c];
    if (i < NN) {
        g_rowptr[p][i + 1] = incl;
        g_cursor[p][i]     = incl - v;
        g_cnt[p][i]        = 0;           // reset for next replay
    }
    if (i == 0) g_rowptr[p][0] = 0;
}

// ---------------- K5: scatter into CSR (slim: cursor + csrc only) ------------
__global__ void scatter_kernel(const int* __restrict__ src_a,
                               const int* __restrict__ dst_a,
                               const int* __restrict__ src_b,
                               const int* __restrict__ dst_b) {
    int i = blockIdx.x * blockDim.x + threadIdx.x;
    if (i >= 2 * EE) return;
    int p = (i >= EE) ? 1 : 0;
    int e = i - p * EE;
    int s = p ? src_b[e] : src_a[e];
    int d = p ? dst_b[e] : dst_a[e];
    int pos = atomicAdd(&g_cursor[p][d], 1);
    g_csrc[p][pos] = s;
}

// ---------------- K6: per-dst aggregation + softmax + bias + ELU -------------
// 128 threads per block; 2 dsts per block; 64 threads per (dst, metapath).
__global__ __launch_bounds__(128) void agg_kernel(const float* __restrict__ bias_a,
                                                  const float* __restrict__ bias_b) {
    const int d = blockIdx.x * 2 + (threadIdx.x >> 6);
    const int p = blockIdx.y;
    const int t = threadIdx.x & 63;          // 0..63
    const int start = g_rowptr[p][d];
    const int end   = g_rowptr[p][d + 1];
    const int hd = t >> 3;                   // head for cols [t*4, t*4+4)

    const float er = __ldg(&g_er[p][d * HEADS + hd]);
    const __half* fbase = &g_feat16[p][0];
    const float*  elbase = &g_el[p][0];
    const int*    csrc   = &g_csrc[p][0];

    float4 acc = make_float4(0.f, 0.f, 0.f, 0.f);
    float den = 0.0f;

    int j = start;
    for (; j + 1 < end; j += 2) {
        int s0 = csrc[j];
        int s1 = csrc[j + 1];
        float el0 = __ldg(&elbase[s0 * HEADS + hd]);
        float el1 = __ldg(&elbase[s1 * HEADS + hd]);
        uint2 r0 = *(const uint2*)&fbase[s0 * FF + t * 4];
        uint2 r1 = *(const uint2*)&fbase[s1 * FF + t * 4];
        float x0 = el0 + er; x0 = (x0 > 0.0f) ? x0 : 0.2f * x0;
        float x1 = el1 + er; x1 = (x1 > 0.0f) ? x1 : 0.2f * x1;
        float ex0 = __expf(x0);
        float ex1 = __expf(x1);
        den += ex0 + ex1;
        float2 a0 = __half22float2(*(const __half2*)&r0.x);
        float2 b0 = __half22float2(*(const __half2*)&r0.y);
        float2 a1 = __half22float2(*(const __half2*)&r1.x);
        float2 b1 = __half22float2(*(const __half2*)&r1.y);
        acc.x += a0.x * ex0 + a1.x * ex1;
        acc.y += a0.y * ex0 + a1.y * ex1;
        acc.z += b0.x * ex0 + b1.x * ex1;
        acc.w += b0.y * ex0 + b1.y * ex1;
    }
    if (j < end) {
        int s0 = csrc[j];
        float el0 = __ldg(&elbase[s0 * HEADS + hd]);
        uint2 r0 = *(const uint2*)&fbase[s0 * FF + t * 4];
        float x0 = el0 + er; x0 = (x0 > 0.0f) ? x0 : 0.2f * x0;
        float ex0 = __expf(x0);
        den += ex0;
        float2 a0 = __half22float2(*(const __half2*)&r0.x);
        float2 b0 = __half22float2(*(const __half2*)&r0.y);
        acc.x += a0.x * ex0;
        acc.y += a0.y * ex0;
        acc.z += b0.x * ex0;
        acc.w += b0.y * ex0;
    }

    float invd = (den > 0.0f) ? 1.0f / den : 1.0f;
    const float* bias = p ? bias_b : bias_a;
    float4 bv = *(const float4*)&bias[t * 4];
    float4 z;
    z.x = acc.x * invd + bv.x;
    z.y = acc.y * invd + bv.y;
    z.z = acc.z * invd + bv.z;
    z.w = acc.w * invd + bv.w;
    z.x = (z.x > 0.0f) ? z.x : (expf(z.x) - 1.0f);
    z.y = (z.y > 0.0f) ? z.y : (expf(z.y) - 1.0f);
    z.z = (z.z > 0.0f) ? z.z : (expf(z.z) - 1.0f);
    z.w = (z.w > 0.0f) ? z.w : (expf(z.w) - 1.0f);
    uint2 zo;
    *(__half2*)&zo.x = __floats2half2_rn(z.x, z.y);
    *(__half2*)&zo.y = __floats2half2_rn(z.z, z.w);
    *(uint2*)&g_z16[p][d * FF + t * 4] = zo;
}

// ---------------- K7: fp16 GEMM  q = Z @ Wsem  + fused tanh.wsem reduce ------
// M=2*NN, K=256, N=128. BK2=32 halves per k-tile (2 k16 mma steps).
#define BK2   32
#define APAD2 8
#define BPAD2 8
__global__ __launch_bounds__(256) void gemm2_kernel(
    const float* __restrict__ Wsem,
    const float* __restrict__ bsem,
    const float* __restrict__ wsem) {
    __shared__ __half As[GBM][BK2 + APAD2];   // m-major
    __shared__ __half Bs[GBN][BK2 + BPAD2];   // n-major (transposed fill)
    const __half* Z = (const __half*)g_z16;
    const int M = 2 * NN;
    const int tid = threadIdx.x;
    const int lane = tid & 31;
    const int wid = tid >> 5;
    const int mBase = (wid >> 1) * 32;
    const int nBase = (wid & 1) * 32;
    const int rowBase = blockIdx.y * GBM;
    const int colBase = blockIdx.x * GBN;

    float acc[2][4][4];
#pragma unroll
    for (int mf = 0; mf < 2; mf++)
#pragma unroll
        for (int nf = 0; nf < 4; nf++)
#pragma unroll
            for (int c = 0; c < 4; c++) acc[mf][nf][c] = 0.0f;

    for (int k0 = 0; k0 < FF; k0 += BK2) {
        // A tile: 128 rows x 32 halves = 512 uint4 (8 halves each)
#pragma unroll
        for (int it = 0; it < 2; it++) {
            int idx = tid + it * 256;
            int r = idx >> 2, q = idx & 3;     // q-th group of 8 halves
            int gr = rowBase + r;
            uint4 v = make_uint4(0u, 0u, 0u, 0u);
            if (gr < M) v = *(const uint4*)&Z[gr * FF + k0 + q * 8];
            *(uint4*)&As[r][q * 8] = v;
        }
        // B tile: Wsem[k0..k0+31][colBase..+63] fp32 -> Bs[n][k] halves
#pragma unroll
        for (int it = 0; it < 2; it++) {
            int slot = tid * 2 + it;           // 0..511
            int r = slot >> 4, c4 = slot & 15; // k-row, 4-col group
            float4 v = *(const float4*)&Wsem[(k0 + r) * SEM_HID + colBase + c4 * 4];
            Bs[c4 * 4 + 0][r] = __float2half_rn(v.x);
            Bs[c4 * 4 + 1][r] = __float2half_rn(v.y);
            Bs[c4 * 4 + 2][r] = __float2half_rn(v.z);
            Bs[c4 * 4 + 3][r] = __float2half_rn(v.w);
        }
        __syncthreads();
#pragma unroll
        for (int ks = 0; ks < BK2; ks += 16) {
            uint32_t a[2][4], b[4][2];
#pragma unroll
            for (int mf = 0; mf < 2; mf++) {
                int row = mBase + mf * 16 + (lane >> 2);
                int kc = ks + 2 * (lane & 3);
                a[mf][0] = *(const uint32_t*)&As[row][kc];
                a[mf][1] = *(const uint32_t*)&As[row + 8][kc];
                a[mf][2] = *(const uint32_t*)&As[row][kc + 8];
                a[mf][3] = *(const uint32_t*)&As[row + 8][kc + 8];
            }
#pragma unroll
            for (int nf = 0; nf < 4; nf++) {
                int col = nBase + nf * 8 + (lane >> 2);
                int kc = ks + 2 * (lane & 3);
                b[nf][0] = *(const uint32_t*)&Bs[col][kc];
                b[nf][1] = *(const uint32_t*)&Bs[col][kc + 8];
            }
#pragma unroll
            for (int mf = 0; mf < 2; mf++)
#pragma unroll
                for (int nf = 0; nf < 4; nf++)
                    mma_f16(acc[mf][nf], a[mf][0], a[mf][1], a[mf][2], a[mf][3],
                            b[nf][0], b[nf][1]);
        }
        __syncthreads();
    }

    // ---- epilogue: tanh(q + bsem) . wsem, reduce, atomic into g_qsum --------
    float bsv[8], wsv[8];
#pragma unroll
    for (int nf = 0; nf < 4; nf++) {
        int gc = colBase + nBase + nf * 8 + 2 * (lane & 3);
        bsv[nf * 2 + 0] = bsem[gc];
        bsv[nf * 2 + 1] = bsem[gc + 1];
        wsv[nf * 2 + 0] = wsem[gc];
        wsv[nf * 2 + 1] = wsem[gc + 1];
    }
    float sp0 = 0.0f, sp1 = 0.0f;
#pragma unroll
    for (int mf = 0; mf < 2; mf++) {
#pragma unroll
        for (int half = 0; half < 2; half++) {
            int gr = rowBase + mBase + mf * 16 + half * 8 + (lane >> 2);
            if (gr < M) {
                float rs = 0.0f;
#pragma unroll
                for (int nf = 0; nf < 4; nf++) {
                    rs += tanh_fast(acc[mf][nf][half * 2 + 0] + bsv[nf * 2 + 0]) * wsv[nf * 2 + 0];
                    rs += tanh_fast(acc[mf][nf][half * 2 + 1] + bsv[nf * 2 + 1]) * wsv[nf * 2 + 1];
                }
                if (gr < NN) sp0 += rs; else sp1 += rs;
            }
        }
    }
#pragma unroll
    for (int o = 16; o > 0; o >>= 1) {
        sp0 += __shfl_down_sync(0xffffffffu, sp0, o);
        sp1 += __shfl_down_sync(0xffffffffu, sp1, o);
    }
    __shared__ float sh[8][2];
    if (lane == 0) { sh[wid][0] = sp0; sh[wid][1] = sp1; }
    __syncthreads();
    if (tid == 0) {
        float s0 = 0.f, s1 = 0.f;
#pragma unroll
        for (int k = 0; k < 8; k++) { s0 += sh[k][0]; s1 += sh[k][1]; }
        if (s0 != 0.0f) atomicAdd(&g_qsum[0], s0);
        if (s1 != 0.0f) atomicAdd(&g_qsum[1], s1);
    }
}

// ---------------- K9: combine with semantic softmax (fp16 z -> fp32 out) -----
__global__ void combine_kernel(float4* __restrict__ out) {
    int i = blockIdx.x * blockDim.x + threadIdx.x;
    if (i >= NN * FF / 4) return;
    float q0 = g_qsum[0] * (1.0f / NN);
    float q1 = g_qsum[1] * (1.0f / NN);
    float mx = fmaxf(q0, q1);
    float b0 = __expf(q0 - mx);
    float b1 = __expf(q1 - mx);
    float inv = 1.0f / (b0 + b1);
    b0 *= inv; b1 *= inv;
    uint2 u0 = *(const uint2*)&g_z16[0][i * 4];
    uint2 u1 = *(const uint2*)&g_z16[1][i * 4];
    float2 a0 = __half22float2(*(const __half2*)&u0.x);
    float2 a1 = __half22float2(*(const __half2*)&u0.y);
    float2 c0 = __half22float2(*(const __half2*)&u1.x);
    float2 c1 = __half22float2(*(const __half2*)&u1.y);
    float4 r;
    r.x = a0.x * b0 + c0.x * b1;
    r.y = a0.y * b0 + c0.y * b1;
    r.z = a1.x * b0 + c1.x * b1;
    r.w = a1.y * b0 + c1.y * b1;
    out[i] = r;
}

// ---------------- launch -----------------------------------------------------
extern "C" void kernel_launch(void* const* d_in, const int* in_sizes, int n_in,
                              void* d_out, int out_size) {
    const float* h      = (const float*)d_in[0];
    const int*   src_a  = (const int*)  d_in[1];
    const int*   dst_a  = (const int*)  d_in[2];
    const int*   src_b  = (const int*)  d_in[3];
    const int*   dst_b  = (const int*)  d_in[4];
    const float* W_a    = (const float*)d_in[5];
    const float* al_a   = (const float*)d_in[6];
    const float* ar_a   = (const float*)d_in[7];
    const float* bias_a = (const float*)d_in[8];
    const float* W_b    = (const float*)d_in[9];
    const float* al_b   = (const float*)d_in[10];
    const float* ar_b   = (const float*)d_in[11];
    const float* bias_b = (const float*)d_in[12];
    const float* Wsem   = (const float*)d_in[13];
    const float* bsem   = (const float*)d_in[14];
    const float* wsem   = (const float*)d_in[15];
    float* out = (float*)d_out;

    (void)in_sizes; (void)n_in; (void)out_size;

    // One-time creation of side stream + events (host objects, no device mem).
    static cudaStream_t s2 = nullptr;
    static cudaEvent_t ev_fork = nullptr, ev_join = nullptr;
    if (s2 == nullptr) {
        cudaStreamCreateWithFlags(&s2, cudaStreamNonBlocking);
        cudaEventCreateWithFlags(&ev_fork, cudaEventDisableTiming);
        cudaEventCreateWithFlags(&ev_join, cudaEventDisableTiming);
    }

    // ---- fork: CSR build on s2, projection GEMM on main stream --------------
    cudaEventRecord(ev_fork, 0);
    cudaStreamWaitEvent(s2, ev_fork, 0);

    // s2 branch: count -> scan -> scatter (depends only on edge lists)
    count_kernel<<<(2 * EE + 255) / 256, 256, 0, s2>>>(dst_a, dst_b);
    {
        dim3 grid(NCHUNK, 2);
        reduce_kernel<<<grid, 256, 0, s2>>>();
        bscan_kernel<<<2, 32, 0, s2>>>();
        scanapply_kernel<<<grid, 1024, 0, s2>>>();
    }
    scatter_kernel<<<(2 * EE + 255) / 256, 256, 0, s2>>>(src_a, dst_a, src_b, dst_b);
    cudaEventRecord(ev_join, s2);

    // main branch: projection GEMM (tf32 TC) + fused el/er
    {
        dim3 grid((2 * FF) / GBN, (NN + GBM - 1) / GBM);
        gemm1_kernel<<<grid, 256>>>(h, W_a, W_b, al_a, ar_a, al_b, ar_b);
    }

    // ---- join ----------------------------------------------------------------
    cudaStreamWaitEvent(0, ev_join, 0);

    {   // gather aggregation + softmax + bias + ELU (2 dsts per block)
        dim3 grid(NN / 2, 2);
        agg_kernel<<<grid, 128>>>(bias_a, bias_b);
    }

    {   // semantic GEMM (fp16 TC) + fused tanh.wsem reduction
        dim3 grid(SEM_HID / GBN, (2 * NN + GBM - 1) / GBM);
        gemm2_kernel<<<grid, 256>>>(Wsem, bsem, wsem);
    }

    combine_kernel<<<(NN * FF / 4 + 255) / 256, 256>>>((float4*)out);
}